// round 7
// baseline (speedup 1.0000x reference)
#include <cuda_runtime.h>
#include <cuda_bf16.h>
#include <cstdint>

// EGNN layer: B=2, N=768, D=32, DM=64, K=16
#define NB 2
#define NN 768
#define DD 32
#define DMC 64
#define KNN 16
#define TJ 256
#define NTILES (NN / TJ)
#define THREADS 256

typedef unsigned int u32;
typedef unsigned long long u64;

// ---- bf16 split helpers ----
__device__ __forceinline__ void splitpair(float v0, float v1, u32& hi, u32& lo) {
    __nv_bfloat162 h = __floats2bfloat162_rn(v0, v1);
    const float l0 = v0 - __low2float(h);
    const float l1 = v1 - __high2float(h);
    __nv_bfloat162 l = __floats2bfloat162_rn(l0, l1);
    hi = *reinterpret_cast<u32*>(&h);
    lo = *reinterpret_cast<u32*>(&l);
}

// m16n8k16 row.col f32.bf16.bf16.f32
__device__ __forceinline__ void mma16816(float* c, const u32* a, u32 b0, u32 b1) {
    asm volatile(
        "mma.sync.aligned.m16n8k16.row.col.f32.bf16.bf16.f32 "
        "{%0,%1,%2,%3}, {%4,%5,%6,%7}, {%8,%9}, {%0,%1,%2,%3};"
        : "+f"(c[0]), "+f"(c[1]), "+f"(c[2]), "+f"(c[3])
        : "r"(a[0]), "r"(a[1]), "r"(a[2]), "r"(a[3]), "r"(b0), "r"(b1));
}

// Per-node precomputed e0 partials (folded with BN affine)
__device__ float g_As[NB * NN * DMC];   // (h_j @ W_top) * s0
__device__ float g_Bs[NB * NN * DMC];   // (h_i @ W_mid + b0) * s0 + t0

__global__ void precompute_kernel(const float* __restrict__ h,
                                  const float* __restrict__ e0W,
                                  const float* __restrict__ e0b,
                                  const float* __restrict__ e0s,
                                  const float* __restrict__ e0t) {
    __shared__ float hv[DD];
    const int node = blockIdx.x;
    const int c = threadIdx.x;
    if (c < DD) hv[c] = h[node * DD + c];
    __syncthreads();
    float a1 = 0.f, a2 = 0.f;
#pragma unroll
    for (int d = 0; d < DD; d++) {
        const float hh = hv[d];
        a1 = fmaf(hh, e0W[d * DMC + c], a1);
        a2 = fmaf(hh, e0W[(DD + d) * DMC + c], a2);
    }
    const float s = e0s[c];
    g_As[node * DMC + c] = a1 * s;
    g_Bs[node * DMC + c] = (a2 + e0b[c]) * s + e0t[c];
}

// ---------------------------------------------------------------------------
// B fragments stored paired: flat u64 index (ks*4 + (nt>>1))*64 + lane*2 + (nt&1)
// so a ulonglong2 LDS.128 fetches the fragments for nt=2np and nt=2np+1.
struct __align__(16) SmemLayout {
    u64 B1h[1024], B1l[1024];    // e1W folded, hi/lo  (8KB each)
    u64 B2h[1024], B2l[1024];    // c0W folded, hi/lo
    float xs[NN * 3];
    float d2all[NN];
    float stage[KNN][DMC];       // f2 rows of selected neighbors
    float Bsi[DMC], wds[DMC], bias1[DMC], bias2[DMC], c1wf[DMC], mnode[DMC];
    int   slotmap[NN];
    float selval[KNN];
    float xsum[3];
    float redv[8];
    int   redi[8];
    int   seli[KNN];
};

__global__ void __launch_bounds__(THREADS, 2)
egnn_main_kernel(const float* __restrict__ x, const float* __restrict__ h,
                 const float* __restrict__ e0W, const float* __restrict__ e0s,
                 const float* __restrict__ e1W, const float* __restrict__ e1b,
                 const float* __restrict__ e1s, const float* __restrict__ e1t,
                 const float* __restrict__ c0W, const float* __restrict__ c0b,
                 const float* __restrict__ c0s, const float* __restrict__ c0t,
                 const float* __restrict__ c1W, const float* __restrict__ c1b,
                 const float* __restrict__ c1s, const float* __restrict__ c1t,
                 const float* __restrict__ n0W, const float* __restrict__ n0b,
                 const float* __restrict__ n0s, const float* __restrict__ n0t,
                 float* __restrict__ out) {
    extern __shared__ char smraw[];
    SmemLayout* sm = reinterpret_cast<SmemLayout*>(smraw);

    const int bi = blockIdx.x;
    const int b  = bi / NN;
    const int i  = bi - b * NN;
    const int t  = threadIdx.x;
    const int w  = t >> 5;
    const int lane = t & 31;
    const int g  = lane >> 2;
    const int tg = lane & 3;

    // ---- fold weights into paired per-lane B-fragment layout ----
    for (int e = t; e < 1024; e += THREADS) {
        const int l  = e & 31;
        const int nt = (e >> 5) & 7;
        const int ks = e >> 8;
        const int k0 = ks * 16 + 2 * (l & 3);
        const int n  = nt * 8 + (l >> 2);
        const int dst = (ks * 4 + (nt >> 1)) * 64 + l * 2 + (nt & 1);
        const float s1 = e1s[n], s2 = c0s[n];
        u32 h0, l0, h1, l1;
        splitpair(e1W[k0 * DMC + n] * s1, e1W[(k0 + 1) * DMC + n] * s1, h0, l0);
        splitpair(e1W[(k0 + 8) * DMC + n] * s1, e1W[(k0 + 9) * DMC + n] * s1, h1, l1);
        sm->B1h[dst] = (u64)h0 | ((u64)h1 << 32);
        sm->B1l[dst] = (u64)l0 | ((u64)l1 << 32);
        splitpair(c0W[k0 * DMC + n] * s2, c0W[(k0 + 1) * DMC + n] * s2, h0, l0);
        splitpair(c0W[(k0 + 8) * DMC + n] * s2, c0W[(k0 + 9) * DMC + n] * s2, h1, l1);
        sm->B2h[dst] = (u64)h0 | ((u64)h1 << 32);
        sm->B2l[dst] = (u64)l0 | ((u64)l1 << 32);
    }
    if (t < DMC) {
        sm->bias1[t] = e1b[t] * e1s[t] + e1t[t];
        sm->bias2[t] = c0b[t] * c0s[t] + c0t[t];
        sm->Bsi[t]   = g_Bs[bi * DMC + t];
        sm->wds[t]   = e0W[2 * DD * DMC + t] * e0s[t];
        sm->c1wf[t]  = c1W[t] * c1s[0];
    }
    for (int e = t; e < NN * 3; e += THREADS) sm->xs[e] = x[b * NN * 3 + e];
    for (int e = t; e < NN; e += THREADS) sm->slotmap[e] = -1;
    if (t == 0) { sm->xsum[0] = 0.f; sm->xsum[1] = 0.f; sm->xsum[2] = 0.f; }
    const float c1bf = c1b[0] * c1s[0] + c1t[0];
    __syncthreads();

    const float xi0 = sm->xs[i * 3 + 0];
    const float xi1 = sm->xs[i * 3 + 1];
    const float xi2 = sm->xs[i * 3 + 2];

    // ---- distances ----
    for (int j = t; j < NN; j += THREADS) {
        const float dx = sm->xs[j * 3 + 0] - xi0;
        const float dy = sm->xs[j * 3 + 1] - xi1;
        const float dz = sm->xs[j * 3 + 2] - xi2;
        sm->d2all[j] = dx * dx + dy * dy + dz * dz;
    }
    __syncthreads();

    // ---- kNN: 16 sequential block argmins (tie-break lower index) ----
    const float INF = __int_as_float(0x7f800000);
    for (int s = 0; s < KNN; s++) {
        float bv = INF; int bidx = NN;
#pragma unroll
        for (int j = t; j < NN; j += THREADS) {
            const float v = sm->d2all[j];
            if (v < bv || (v == bv && j < bidx)) { bv = v; bidx = j; }
        }
#pragma unroll
        for (int off = 16; off; off >>= 1) {
            const float ov = __shfl_down_sync(0xffffffffu, bv, off);
            const int   oi = __shfl_down_sync(0xffffffffu, bidx, off);
            if (ov < bv || (ov == bv && oi < bidx)) { bv = ov; bidx = oi; }
        }
        if (lane == 0) { sm->redv[w] = bv; sm->redi[w] = bidx; }
        __syncthreads();
        if (t == 0) {
            float fv = sm->redv[0]; int fi = sm->redi[0];
#pragma unroll
            for (int q = 1; q < 8; q++) {
                const float wv = sm->redv[q]; const int wi = sm->redi[q];
                if (wv < fv || (wv == fv && wi < fi)) { fv = wv; fi = wi; }
            }
            sm->seli[s] = fi;
            sm->selval[s] = fv;
            sm->d2all[fi] = INF;
        }
        __syncthreads();
    }
    if (t < KNN) {
        sm->d2all[sm->seli[t]] = sm->selval[t];   // restore
        sm->slotmap[sm->seli[t]] = t;
    }
    __syncthreads();

    // ---- barrier-free mainloop: 8 warps x 32 rows, TJ=256 ----
    float xacc0 = 0.f, xacc1 = 0.f, xacc2 = 0.f;
    const float* As_b = g_As + (size_t)(b * NN) * DMC;

    for (int tile = 0; tile < NTILES; tile++) {
        const int base = tile * TJ + w * 32;
        int rows[4];
        rows[0] = base + g;       rows[1] = base + g + 8;
        rows[2] = base + 16 + g;  rows[3] = base + 24 + g;
        float d2v[4];
#pragma unroll
        for (int q = 0; q < 4; q++) d2v[q] = sm->d2all[rows[q]];

        // ---------------- GEMM 1 with on-the-fly A build + 1-ks prefetch ----
        float acc[64];           // acc[blk*32 + nt*4 + q]
#pragma unroll
        for (int q = 0; q < 64; q++) acc[q] = 0.f;

        float2 pA[8];            // [blk*4 + {rowg_k0, rowg8_k0, rowg_k8, rowg8_k8}]
#pragma unroll
        for (int blk = 0; blk < 2; blk++) {
            const float* R0 = As_b + rows[blk * 2 + 0] * DMC + 2 * tg;
            const float* R1 = As_b + rows[blk * 2 + 1] * DMC + 2 * tg;
            pA[blk * 4 + 0] = *reinterpret_cast<const float2*>(R0);
            pA[blk * 4 + 1] = *reinterpret_cast<const float2*>(R1);
            pA[blk * 4 + 2] = *reinterpret_cast<const float2*>(R0 + 8);
            pA[blk * 4 + 3] = *reinterpret_cast<const float2*>(R1 + 8);
        }

#pragma unroll
        for (int ks = 0; ks < 4; ks++) {
            const int k0 = ks * 16 + 2 * tg;
            const float2 bs0 = *reinterpret_cast<const float2*>(&sm->Bsi[k0]);
            const float2 bs1 = *reinterpret_cast<const float2*>(&sm->Bsi[k0 + 8]);
            const float2 wd0 = *reinterpret_cast<const float2*>(&sm->wds[k0]);
            const float2 wd1 = *reinterpret_cast<const float2*>(&sm->wds[k0 + 8]);
            u32 ah[2][4], al[2][4];
#pragma unroll
            for (int blk = 0; blk < 2; blk++) {
                const float da = d2v[blk * 2 + 0], db = d2v[blk * 2 + 1];
                float v0 = fmaxf(fmaf(da, wd0.x, pA[blk * 4 + 0].x + bs0.x), 0.f);
                float v1 = fmaxf(fmaf(da, wd0.y, pA[blk * 4 + 0].y + bs0.y), 0.f);
                splitpair(v0, v1, ah[blk][0], al[blk][0]);
                v0 = fmaxf(fmaf(db, wd0.x, pA[blk * 4 + 1].x + bs0.x), 0.f);
                v1 = fmaxf(fmaf(db, wd0.y, pA[blk * 4 + 1].y + bs0.y), 0.f);
                splitpair(v0, v1, ah[blk][1], al[blk][1]);
                v0 = fmaxf(fmaf(da, wd1.x, pA[blk * 4 + 2].x + bs1.x), 0.f);
                v1 = fmaxf(fmaf(da, wd1.y, pA[blk * 4 + 2].y + bs1.y), 0.f);
                splitpair(v0, v1, ah[blk][2], al[blk][2]);
                v0 = fmaxf(fmaf(db, wd1.x, pA[blk * 4 + 3].x + bs1.x), 0.f);
                v1 = fmaxf(fmaf(db, wd1.y, pA[blk * 4 + 3].y + bs1.y), 0.f);
                splitpair(v0, v1, ah[blk][3], al[blk][3]);
            }
            if (ks < 3) {
                const int kn = (ks + 1) * 16 + 2 * tg;
#pragma unroll
                for (int blk = 0; blk < 2; blk++) {
                    const float* R0 = As_b + rows[blk * 2 + 0] * DMC + kn;
                    const float* R1 = As_b + rows[blk * 2 + 1] * DMC + kn;
                    pA[blk * 4 + 0] = *reinterpret_cast<const float2*>(R0);
                    pA[blk * 4 + 1] = *reinterpret_cast<const float2*>(R1);
                    pA[blk * 4 + 2] = *reinterpret_cast<const float2*>(R0 + 8);
                    pA[blk * 4 + 3] = *reinterpret_cast<const float2*>(R1 + 8);
                }
            }
#pragma unroll
            for (int np = 0; np < 4; np++) {
                const ulonglong2 bh2 = *reinterpret_cast<const ulonglong2*>(
                    &sm->B1h[(ks * 4 + np) * 64 + 2 * lane]);
                const ulonglong2 bl2 = *reinterpret_cast<const ulonglong2*>(
                    &sm->B1l[(ks * 4 + np) * 64 + 2 * lane]);
#pragma unroll
                for (int sub = 0; sub < 2; sub++) {
                    const u64 bh = sub ? bh2.y : bh2.x;
                    const u64 bl = sub ? bl2.y : bl2.x;
                    const u32 bh0 = (u32)bh, bh1 = (u32)(bh >> 32);
                    const u32 bl0 = (u32)bl, bl1 = (u32)(bl >> 32);
                    const int nt = 2 * np + sub;
#pragma unroll
                    for (int blk = 0; blk < 2; blk++) {
                        float* ac = acc + blk * 32 + nt * 4;
                        mma16816(ac, ah[blk], bh0, bh1);
                        mma16816(ac, al[blk], bh0, bh1);
                        mma16816(ac, ah[blk], bl0, bl1);
                    }
                }
            }
        }

        // ---------------- epilogue 1: relu+bias, stage, re-split into A2 ----
        int slot[4];
#pragma unroll
        for (int q = 0; q < 4; q++) slot[q] = sm->slotmap[rows[q]];
        u32 ah2[2][16], al2[2][16];
#pragma unroll
        for (int nt = 0; nt < 8; nt++) {
            const int n0 = nt * 8 + 2 * tg;
            const float2 bb = *reinterpret_cast<const float2*>(&sm->bias1[n0]);
            const int ks2 = nt >> 1, hh = (nt & 1) * 2;
#pragma unroll
            for (int blk = 0; blk < 2; blk++) {
                const float* ac = acc + blk * 32 + nt * 4;
                const float v0 = fmaxf(ac[0] + bb.x, 0.f);
                const float v1 = fmaxf(ac[1] + bb.y, 0.f);
                const float v2 = fmaxf(ac[2] + bb.x, 0.f);
                const float v3 = fmaxf(ac[3] + bb.y, 0.f);
                if (slot[blk * 2 + 0] >= 0)
                    *reinterpret_cast<float2*>(&sm->stage[slot[blk * 2 + 0]][n0]) =
                        make_float2(v0, v1);
                if (slot[blk * 2 + 1] >= 0)
                    *reinterpret_cast<float2*>(&sm->stage[slot[blk * 2 + 1]][n0]) =
                        make_float2(v2, v3);
                splitpair(v0, v1, ah2[blk][ks2 * 4 + hh + 0], al2[blk][ks2 * 4 + hh + 0]);
                splitpair(v2, v3, ah2[blk][ks2 * 4 + hh + 1], al2[blk][ks2 * 4 + hh + 1]);
            }
        }

        // ---------------- GEMM 2 in two N-halves + c1 dot ----
        float dot[4] = {0.f, 0.f, 0.f, 0.f};
#pragma unroll
        for (int hf = 0; hf < 2; hf++) {
            float acc2[32];
#pragma unroll
            for (int q = 0; q < 32; q++) acc2[q] = 0.f;
#pragma unroll
            for (int ks = 0; ks < 4; ks++) {
#pragma unroll
                for (int npl = 0; npl < 2; npl++) {
                    const int np = 2 * hf + npl;
                    const ulonglong2 bh2 = *reinterpret_cast<const ulonglong2*>(
                        &sm->B2h[(ks * 4 + np) * 64 + 2 * lane]);
                    const ulonglong2 bl2 = *reinterpret_cast<const ulonglong2*>(
                        &sm->B2l[(ks * 4 + np) * 64 + 2 * lane]);
#pragma unroll
                    for (int sub = 0; sub < 2; sub++) {
                        const u64 bh = sub ? bh2.y : bh2.x;
                        const u64 bl = sub ? bl2.y : bl2.x;
                        const u32 bh0 = (u32)bh, bh1 = (u32)(bh >> 32);
                        const u32 bl0 = (u32)bl, bl1 = (u32)(bl >> 32);
                        const int ntl = 2 * npl + sub;
#pragma unroll
                        for (int blk = 0; blk < 2; blk++) {
                            float* ac = acc2 + blk * 16 + ntl * 4;
                            mma16816(ac, ah2[blk] + ks * 4, bh0, bh1);
                            mma16816(ac, al2[blk] + ks * 4, bh0, bh1);
                            mma16816(ac, ah2[blk] + ks * 4, bl0, bl1);
                        }
                    }
                }
            }
#pragma unroll
            for (int ntl = 0; ntl < 4; ntl++) {
                const int n0 = (4 * hf + ntl) * 8 + 2 * tg;
                const float2 bb = *reinterpret_cast<const float2*>(&sm->bias2[n0]);
                const float2 cw = *reinterpret_cast<const float2*>(&sm->c1wf[n0]);
#pragma unroll
                for (int blk = 0; blk < 2; blk++) {
                    const float* ac = acc2 + blk * 16 + ntl * 4;
                    const float v0 = fmaxf(ac[0] + bb.x, 0.f);
                    const float v1 = fmaxf(ac[1] + bb.y, 0.f);
                    const float v2 = fmaxf(ac[2] + bb.x, 0.f);
                    const float v3 = fmaxf(ac[3] + bb.y, 0.f);
                    dot[blk * 2 + 0] = fmaf(v0, cw.x, fmaf(v1, cw.y, dot[blk * 2 + 0]));
                    dot[blk * 2 + 1] = fmaf(v2, cw.x, fmaf(v3, cw.y, dot[blk * 2 + 1]));
                }
            }
        }

        // reduce dots over the 4 lanes of each row group (tg)
#pragma unroll
        for (int q = 0; q < 4; q++) {
            dot[q] += __shfl_xor_sync(0xffffffffu, dot[q], 1);
            dot[q] += __shfl_xor_sync(0xffffffffu, dot[q], 2);
        }
        if (tg == 0) {
#pragma unroll
            for (int q = 0; q < 4; q++) {
                const float ww = fmaxf(dot[q] + c1bf, 0.f);
                const int r = rows[q];
                xacc0 = fmaf(ww, sm->xs[r * 3 + 0] - xi0, xacc0);
                xacc1 = fmaf(ww, sm->xs[r * 3 + 1] - xi1, xacc1);
                xacc2 = fmaf(ww, sm->xs[r * 3 + 2] - xi2, xacc2);
            }
        }
    }

    // ---- reduce coordinate update ----
#pragma unroll
    for (int off = 16; off; off >>= 1) {
        xacc0 += __shfl_down_sync(0xffffffffu, xacc0, off);
        xacc1 += __shfl_down_sync(0xffffffffu, xacc1, off);
        xacc2 += __shfl_down_sync(0xffffffffu, xacc2, off);
    }
    if (lane == 0) {
        atomicAdd(&sm->xsum[0], xacc0);
        atomicAdd(&sm->xsum[1], xacc1);
        atomicAdd(&sm->xsum[2], xacc2);
    }
    __syncthreads();   // stage + xsum complete

    // ---- m_node from staged rows ----
    if (t < DMC) {
        float m = 0.f;
#pragma unroll
        for (int s = 0; s < KNN; s++) m += sm->stage[s][t];
        sm->mnode[t] = m;
    }
    __syncthreads();

    // ---- outputs ----
    if (t < 3) out[bi * 3 + t] = sm->xs[i * 3 + t] + sm->xsum[t];
    if (t < DD) {
        float acc = 0.f;
        const float* hrow = h + bi * DD;
#pragma unroll
        for (int k = 0; k < DD; k++) acc = fmaf(hrow[k], n0W[k * DD + t], acc);
#pragma unroll
        for (int k = 0; k < DMC; k++) acc = fmaf(sm->mnode[k], n0W[(DD + k) * DD + t], acc);
        const float v = (acc + n0b[t]) * n0s[t] + n0t[t];
        out[NB * NN * 3 + bi * DD + t] = fmaxf(v, 0.f);
    }
}

// ---------------------------------------------------------------------------
extern "C" void kernel_launch(void* const* d_in, const int* in_sizes, int n_in,
                              void* d_out, int out_size) {
    const float* x   = (const float*)d_in[0];
    const float* h   = (const float*)d_in[1];
    const float* e0W = (const float*)d_in[2];
    const float* e0b = (const float*)d_in[3];
    const float* e0s = (const float*)d_in[4];
    const float* e0t = (const float*)d_in[5];
    const float* e1W = (const float*)d_in[6];
    const float* e1b = (const float*)d_in[7];
    const float* e1s = (const float*)d_in[8];
    const float* e1t = (const float*)d_in[9];
    const float* c0W = (const float*)d_in[10];
    const float* c0b = (const float*)d_in[11];
    const float* c0s = (const float*)d_in[12];
    const float* c0t = (const float*)d_in[13];
    const float* c1W = (const float*)d_in[14];
    const float* c1b = (const float*)d_in[15];
    const float* c1s = (const float*)d_in[16];
    const float* c1t = (const float*)d_in[17];
    const float* n0W = (const float*)d_in[18];
    const float* n0b = (const float*)d_in[19];
    const float* n0s = (const float*)d_in[20];
    const float* n0t = (const float*)d_in[21];
    float* out = (float*)d_out;

    static_assert(sizeof(SmemLayout) < 100 * 1024, "smem too big");
    cudaFuncSetAttribute(egnn_main_kernel,
                         cudaFuncAttributeMaxDynamicSharedMemorySize,
                         (int)sizeof(SmemLayout));

    precompute_kernel<<<NB * NN, 64>>>(h, e0W, e0b, e0s, e0t);
    egnn_main_kernel<<<NB * NN, THREADS, sizeof(SmemLayout)>>>(
        x, h, e0W, e0s,
        e1W, e1b, e1s, e1t,
        c0W, c0b, c0s, c0t,
        c1W, c1b, c1s, c1t,
        n0W, n0b, n0s, n0t,
        out);
}

// round 8
// speedup vs baseline: 1.0856x; 1.0856x over previous
#include <cuda_runtime.h>
#include <cuda_bf16.h>
#include <cstdint>

// EGNN layer: B=2, N=768, D=32, DM=64, K=16
#define NB 2
#define NN 768
#define DD 32
#define DMC 64
#define KNN 16
#define TJ 128
#define NTILES (NN / TJ)
#define THREADS 256

typedef unsigned int u32;
typedef unsigned long long u64;

// ---- bf16 split helpers ----
__device__ __forceinline__ void splitpair(float v0, float v1, u32& hi, u32& lo) {
    __nv_bfloat162 h = __floats2bfloat162_rn(v0, v1);
    const float l0 = v0 - __low2float(h);
    const float l1 = v1 - __high2float(h);
    __nv_bfloat162 l = __floats2bfloat162_rn(l0, l1);
    hi = *reinterpret_cast<u32*>(&h);
    lo = *reinterpret_cast<u32*>(&l);
}

// m16n8k16 row.col f32.bf16.bf16.f32
__device__ __forceinline__ void mma16816(float* c, const u32* a, u32 b0, u32 b1) {
    asm volatile(
        "mma.sync.aligned.m16n8k16.row.col.f32.bf16.bf16.f32 "
        "{%0,%1,%2,%3}, {%4,%5,%6,%7}, {%8,%9}, {%0,%1,%2,%3};"
        : "+f"(c[0]), "+f"(c[1]), "+f"(c[2]), "+f"(c[3])
        : "r"(a[0]), "r"(a[1]), "r"(a[2]), "r"(a[3]), "r"(b0), "r"(b1));
}

// Per-node precomputed e0 partials (folded with BN affine)
__device__ float g_As[NB * NN * DMC];   // (h_j @ W_top) * s0
__device__ float g_Bs[NB * NN * DMC];   // (h_i @ W_mid + b0) * s0 + t0

__global__ void precompute_kernel(const float* __restrict__ h,
                                  const float* __restrict__ e0W,
                                  const float* __restrict__ e0b,
                                  const float* __restrict__ e0s,
                                  const float* __restrict__ e0t) {
    __shared__ float hv[DD];
    const int node = blockIdx.x;
    const int c = threadIdx.x;
    if (c < DD) hv[c] = h[node * DD + c];
    __syncthreads();
    float a1 = 0.f, a2 = 0.f;
#pragma unroll
    for (int d = 0; d < DD; d++) {
        const float hh = hv[d];
        a1 = fmaf(hh, e0W[d * DMC + c], a1);
        a2 = fmaf(hh, e0W[(DD + d) * DMC + c], a2);
    }
    const float s = e0s[c];
    g_As[node * DMC + c] = a1 * s;
    g_Bs[node * DMC + c] = (a2 + e0b[c]) * s + e0t[c];
}

// ---------------------------------------------------------------------------
// B-fragment smem: per (kstep 0..3, ntile 0..7, lane 0..31) one u64 = {b0, b1}
struct __align__(16) SmemLayout {
    u64 B1h[1024], B1l[1024];    // e1W folded, hi/lo  (8KB each)
    u64 B2h[1024], B2l[1024];    // c0W folded, hi/lo
    float xs[NN * 3];
    float d2all[NN];
    float stage[KNN][DMC];       // f2 rows of selected neighbors
    float Bsi[DMC], wds[DMC], bias1[DMC], bias2[DMC], c1wf[DMC], mnode[DMC];
    int   slotmap[NN];
    float selval[KNN];
    float xsum[3];
    float redv[8];
    int   redi[8];
    int   seli[KNN];
};

__global__ void __launch_bounds__(THREADS, 3)
egnn_main_kernel(const float* __restrict__ x, const float* __restrict__ h,
                 const float* __restrict__ e0W, const float* __restrict__ e0s,
                 const float* __restrict__ e1W, const float* __restrict__ e1b,
                 const float* __restrict__ e1s, const float* __restrict__ e1t,
                 const float* __restrict__ c0W, const float* __restrict__ c0b,
                 const float* __restrict__ c0s, const float* __restrict__ c0t,
                 const float* __restrict__ c1W, const float* __restrict__ c1b,
                 const float* __restrict__ c1s, const float* __restrict__ c1t,
                 const float* __restrict__ n0W, const float* __restrict__ n0b,
                 const float* __restrict__ n0s, const float* __restrict__ n0t,
                 float* __restrict__ out) {
    extern __shared__ char smraw[];
    SmemLayout* sm = reinterpret_cast<SmemLayout*>(smraw);

    const int bi = blockIdx.x;
    const int b  = bi / NN;
    const int i  = bi - b * NN;
    const int t  = threadIdx.x;
    const int w  = t >> 5;
    const int lane = t & 31;
    const int g  = lane >> 2;
    const int tg = lane & 3;

    // ---- fold weights into per-lane B-fragment layout ----
    for (int e = t; e < 1024; e += THREADS) {
        const int l  = e & 31;
        const int nt = (e >> 5) & 7;
        const int ks = e >> 8;
        const int k0 = ks * 16 + 2 * (l & 3);
        const int n  = nt * 8 + (l >> 2);
        const float s1 = e1s[n], s2 = c0s[n];
        u32 h0, l0, h1, l1;
        splitpair(e1W[k0 * DMC + n] * s1, e1W[(k0 + 1) * DMC + n] * s1, h0, l0);
        splitpair(e1W[(k0 + 8) * DMC + n] * s1, e1W[(k0 + 9) * DMC + n] * s1, h1, l1);
        sm->B1h[e] = (u64)h0 | ((u64)h1 << 32);
        sm->B1l[e] = (u64)l0 | ((u64)l1 << 32);
        splitpair(c0W[k0 * DMC + n] * s2, c0W[(k0 + 1) * DMC + n] * s2, h0, l0);
        splitpair(c0W[(k0 + 8) * DMC + n] * s2, c0W[(k0 + 9) * DMC + n] * s2, h1, l1);
        sm->B2h[e] = (u64)h0 | ((u64)h1 << 32);
        sm->B2l[e] = (u64)l0 | ((u64)l1 << 32);
    }
    if (t < DMC) {
        sm->bias1[t] = e1b[t] * e1s[t] + e1t[t];
        sm->bias2[t] = c0b[t] * c0s[t] + c0t[t];
        sm->Bsi[t]   = g_Bs[bi * DMC + t];
        sm->wds[t]   = e0W[2 * DD * DMC + t] * e0s[t];
        sm->c1wf[t]  = c1W[t] * c1s[0];
    }
    for (int e = t; e < NN * 3; e += THREADS) sm->xs[e] = x[b * NN * 3 + e];
    for (int e = t; e < NN; e += THREADS) sm->slotmap[e] = -1;
    if (t == 0) { sm->xsum[0] = 0.f; sm->xsum[1] = 0.f; sm->xsum[2] = 0.f; }
    const float c1bf = c1b[0] * c1s[0] + c1t[0];
    __syncthreads();

    const float xi0 = sm->xs[i * 3 + 0];
    const float xi1 = sm->xs[i * 3 + 1];
    const float xi2 = sm->xs[i * 3 + 2];

    // ---- distances ----
    for (int j = t; j < NN; j += THREADS) {
        const float dx = sm->xs[j * 3 + 0] - xi0;
        const float dy = sm->xs[j * 3 + 1] - xi1;
        const float dz = sm->xs[j * 3 + 2] - xi2;
        sm->d2all[j] = dx * dx + dy * dy + dz * dz;
    }
    __syncthreads();

    // ---- kNN: 16 sequential block argmins (tie-break lower index) ----
    const float INF = __int_as_float(0x7f800000);
    for (int s = 0; s < KNN; s++) {
        float bv = INF; int bidx = NN;
#pragma unroll
        for (int j = t; j < NN; j += THREADS) {
            const float v = sm->d2all[j];
            if (v < bv || (v == bv && j < bidx)) { bv = v; bidx = j; }
        }
#pragma unroll
        for (int off = 16; off; off >>= 1) {
            const float ov = __shfl_down_sync(0xffffffffu, bv, off);
            const int   oi = __shfl_down_sync(0xffffffffu, bidx, off);
            if (ov < bv || (ov == bv && oi < bidx)) { bv = ov; bidx = oi; }
        }
        if (lane == 0) { sm->redv[w] = bv; sm->redi[w] = bidx; }
        __syncthreads();
        if (t == 0) {
            float fv = sm->redv[0]; int fi = sm->redi[0];
#pragma unroll
            for (int q = 1; q < 8; q++) {
                const float wv = sm->redv[q]; const int wi = sm->redi[q];
                if (wv < fv || (wv == fv && wi < fi)) { fv = wv; fi = wi; }
            }
            sm->seli[s] = fi;
            sm->selval[s] = fv;
            sm->d2all[fi] = INF;
        }
        __syncthreads();
    }
    if (t < KNN) {
        sm->d2all[sm->seli[t]] = sm->selval[t];   // restore
        sm->slotmap[sm->seli[t]] = t;
    }
    __syncthreads();

    // ---- barrier-free mainloop: 8 warps x 16 rows, TJ=128 ----
    float xacc0 = 0.f, xacc1 = 0.f, xacc2 = 0.f;
    const float* As_b = g_As + (size_t)(b * NN) * DMC;

    for (int tile = 0; tile < NTILES; tile++) {
        const int j0 = tile * TJ;
        const int r0 = j0 + w * 16 + g;
        const int r1 = r0 + 8;
        const float d2a = sm->d2all[r0];
        const float d2b = sm->d2all[r1];
        const float* A0 = As_b + r0 * DMC;
        const float* A1 = As_b + r1 * DMC;

        // build A1-fragments in registers: f1 = relu(As + Bsi + d2*wds)
        u32 ah[16], al[16];
#pragma unroll
        for (int ks = 0; ks < 4; ks++) {
            const int k0 = ks * 16 + 2 * tg;
            const float2 bs0 = *reinterpret_cast<const float2*>(&sm->Bsi[k0]);
            const float2 bs1 = *reinterpret_cast<const float2*>(&sm->Bsi[k0 + 8]);
            const float2 wd0 = *reinterpret_cast<const float2*>(&sm->wds[k0]);
            const float2 wd1 = *reinterpret_cast<const float2*>(&sm->wds[k0 + 8]);
            const float2 p0 = *reinterpret_cast<const float2*>(&A0[k0]);
            const float2 q0 = *reinterpret_cast<const float2*>(&A0[k0 + 8]);
            const float2 p1 = *reinterpret_cast<const float2*>(&A1[k0]);
            const float2 q1 = *reinterpret_cast<const float2*>(&A1[k0 + 8]);
            float v0 = fmaxf(fmaf(d2a, wd0.x, p0.x + bs0.x), 0.f);
            float v1 = fmaxf(fmaf(d2a, wd0.y, p0.y + bs0.y), 0.f);
            splitpair(v0, v1, ah[ks * 4 + 0], al[ks * 4 + 0]);
            v0 = fmaxf(fmaf(d2b, wd0.x, p1.x + bs0.x), 0.f);
            v1 = fmaxf(fmaf(d2b, wd0.y, p1.y + bs0.y), 0.f);
            splitpair(v0, v1, ah[ks * 4 + 1], al[ks * 4 + 1]);
            v0 = fmaxf(fmaf(d2a, wd1.x, q0.x + bs1.x), 0.f);
            v1 = fmaxf(fmaf(d2a, wd1.y, q0.y + bs1.y), 0.f);
            splitpair(v0, v1, ah[ks * 4 + 2], al[ks * 4 + 2]);
            v0 = fmaxf(fmaf(d2b, wd1.x, q1.x + bs1.x), 0.f);
            v1 = fmaxf(fmaf(d2b, wd1.y, q1.y + bs1.y), 0.f);
            splitpair(v0, v1, ah[ks * 4 + 3], al[ks * 4 + 3]);
        }

        const int slot0 = sm->slotmap[r0];
        const int slot1 = sm->slotmap[r1];
        u32 ah2[16], al2[16];

        // GEMM 1 in two N-halves (nt 0..3, then 4..7) to cap live registers
#pragma unroll
        for (int hf = 0; hf < 2; hf++) {
            float acc[16];
#pragma unroll
            for (int q = 0; q < 16; q++) acc[q] = 0.f;
#pragma unroll
            for (int ks = 0; ks < 4; ks++) {
#pragma unroll
                for (int ntl = 0; ntl < 4; ntl++) {
                    const int nt = hf * 4 + ntl;
                    const u64 bh = sm->B1h[ks * 256 + nt * 32 + lane];
                    const u64 bl = sm->B1l[ks * 256 + nt * 32 + lane];
                    const u32 bh0 = (u32)bh, bh1 = (u32)(bh >> 32);
                    const u32 bl0 = (u32)bl, bl1 = (u32)(bl >> 32);
                    mma16816(acc + ntl * 4, ah + ks * 4, bh0, bh1);
                    mma16816(acc + ntl * 4, al + ks * 4, bh0, bh1);
                    mma16816(acc + ntl * 4, ah + ks * 4, bl0, bl1);
                }
            }
            // epilogue half: relu+bias, stage, re-split into A2 frags (ks2 = 2hf..2hf+1)
#pragma unroll
            for (int ntl = 0; ntl < 4; ntl++) {
                const int nt = hf * 4 + ntl;
                const int n0 = nt * 8 + 2 * tg;
                const float2 bb = *reinterpret_cast<const float2*>(&sm->bias1[n0]);
                const float v0 = fmaxf(acc[ntl * 4 + 0] + bb.x, 0.f);
                const float v1 = fmaxf(acc[ntl * 4 + 1] + bb.y, 0.f);
                const float v2 = fmaxf(acc[ntl * 4 + 2] + bb.x, 0.f);
                const float v3 = fmaxf(acc[ntl * 4 + 3] + bb.y, 0.f);
                if (slot0 >= 0)
                    *reinterpret_cast<float2*>(&sm->stage[slot0][n0]) = make_float2(v0, v1);
                if (slot1 >= 0)
                    *reinterpret_cast<float2*>(&sm->stage[slot1][n0]) = make_float2(v2, v3);
                const int ks2 = nt >> 1, hh = (nt & 1) * 2;
                splitpair(v0, v1, ah2[ks2 * 4 + hh + 0], al2[ks2 * 4 + hh + 0]);
                splitpair(v2, v3, ah2[ks2 * 4 + hh + 1], al2[ks2 * 4 + hh + 1]);
            }
        }

        // GEMM 2 in two N-halves + c1 dot
        float dot0 = 0.f, dot1 = 0.f;
#pragma unroll
        for (int hf = 0; hf < 2; hf++) {
            float acc[16];
#pragma unroll
            for (int q = 0; q < 16; q++) acc[q] = 0.f;
#pragma unroll
            for (int ks = 0; ks < 4; ks++) {
#pragma unroll
                for (int ntl = 0; ntl < 4; ntl++) {
                    const int nt = hf * 4 + ntl;
                    const u64 bh = sm->B2h[ks * 256 + nt * 32 + lane];
                    const u64 bl = sm->B2l[ks * 256 + nt * 32 + lane];
                    const u32 bh0 = (u32)bh, bh1 = (u32)(bh >> 32);
                    const u32 bl0 = (u32)bl, bl1 = (u32)(bl >> 32);
                    mma16816(acc + ntl * 4, ah2 + ks * 4, bh0, bh1);
                    mma16816(acc + ntl * 4, al2 + ks * 4, bh0, bh1);
                    mma16816(acc + ntl * 4, ah2 + ks * 4, bl0, bl1);
                }
            }
#pragma unroll
            for (int ntl = 0; ntl < 4; ntl++) {
                const int nt = hf * 4 + ntl;
                const int n0 = nt * 8 + 2 * tg;
                const float2 bb = *reinterpret_cast<const float2*>(&sm->bias2[n0]);
                const float2 cw = *reinterpret_cast<const float2*>(&sm->c1wf[n0]);
                const float v0 = fmaxf(acc[ntl * 4 + 0] + bb.x, 0.f);
                const float v1 = fmaxf(acc[ntl * 4 + 1] + bb.y, 0.f);
                const float v2 = fmaxf(acc[ntl * 4 + 2] + bb.x, 0.f);
                const float v3 = fmaxf(acc[ntl * 4 + 3] + bb.y, 0.f);
                dot0 = fmaf(v0, cw.x, fmaf(v1, cw.y, dot0));
                dot1 = fmaf(v2, cw.x, fmaf(v3, cw.y, dot1));
            }
        }
        dot0 += __shfl_xor_sync(0xffffffffu, dot0, 1);
        dot0 += __shfl_xor_sync(0xffffffffu, dot0, 2);
        dot1 += __shfl_xor_sync(0xffffffffu, dot1, 1);
        dot1 += __shfl_xor_sync(0xffffffffu, dot1, 2);
        if (tg == 0) {
            const float w0 = fmaxf(dot0 + c1bf, 0.f);
            const float w1 = fmaxf(dot1 + c1bf, 0.f);
            xacc0 += w0 * (sm->xs[r0 * 3 + 0] - xi0) + w1 * (sm->xs[r1 * 3 + 0] - xi0);
            xacc1 += w0 * (sm->xs[r0 * 3 + 1] - xi1) + w1 * (sm->xs[r1 * 3 + 1] - xi1);
            xacc2 += w0 * (sm->xs[r0 * 3 + 2] - xi2) + w1 * (sm->xs[r1 * 3 + 2] - xi2);
        }
    }

    // ---- reduce coordinate update ----
#pragma unroll
    for (int off = 16; off; off >>= 1) {
        xacc0 += __shfl_down_sync(0xffffffffu, xacc0, off);
        xacc1 += __shfl_down_sync(0xffffffffu, xacc1, off);
        xacc2 += __shfl_down_sync(0xffffffffu, xacc2, off);
    }
    if (lane == 0) {
        atomicAdd(&sm->xsum[0], xacc0);
        atomicAdd(&sm->xsum[1], xacc1);
        atomicAdd(&sm->xsum[2], xacc2);
    }
    __syncthreads();   // stage + xsum complete

    // ---- m_node from staged rows ----
    if (t < DMC) {
        float m = 0.f;
#pragma unroll
        for (int s = 0; s < KNN; s++) m += sm->stage[s][t];
        sm->mnode[t] = m;
    }
    __syncthreads();

    // ---- outputs ----
    if (t < 3) out[bi * 3 + t] = sm->xs[i * 3 + t] + sm->xsum[t];
    if (t < DD) {
        float acc = 0.f;
        const float* hrow = h + bi * DD;
#pragma unroll
        for (int k = 0; k < DD; k++) acc = fmaf(hrow[k], n0W[k * DD + t], acc);
#pragma unroll
        for (int k = 0; k < DMC; k++) acc = fmaf(sm->mnode[k], n0W[(DD + k) * DD + t], acc);
        const float v = (acc + n0b[t]) * n0s[t] + n0t[t];
        out[NB * NN * 3 + bi * DD + t] = fmaxf(v, 0.f);
    }
}

// ---------------------------------------------------------------------------
extern "C" void kernel_launch(void* const* d_in, const int* in_sizes, int n_in,
                              void* d_out, int out_size) {
    const float* x   = (const float*)d_in[0];
    const float* h   = (const float*)d_in[1];
    const float* e0W = (const float*)d_in[2];
    const float* e0b = (const float*)d_in[3];
    const float* e0s = (const float*)d_in[4];
    const float* e0t = (const float*)d_in[5];
    const float* e1W = (const float*)d_in[6];
    const float* e1b = (const float*)d_in[7];
    const float* e1s = (const float*)d_in[8];
    const float* e1t = (const float*)d_in[9];
    const float* c0W = (const float*)d_in[10];
    const float* c0b = (const float*)d_in[11];
    const float* c0s = (const float*)d_in[12];
    const float* c0t = (const float*)d_in[13];
    const float* c1W = (const float*)d_in[14];
    const float* c1b = (const float*)d_in[15];
    const float* c1s = (const float*)d_in[16];
    const float* c1t = (const float*)d_in[17];
    const float* n0W = (const float*)d_in[18];
    const float* n0b = (const float*)d_in[19];
    const float* n0s = (const float*)d_in[20];
    const float* n0t = (const float*)d_in[21];
    float* out = (float*)d_out;

    static_assert(sizeof(SmemLayout) < 76 * 1024, "smem too big for 3 CTAs");
    cudaFuncSetAttribute(egnn_main_kernel,
                         cudaFuncAttributeMaxDynamicSharedMemorySize,
                         (int)sizeof(SmemLayout));

    precompute_kernel<<<NB * NN, 64>>>(h, e0W, e0b, e0s, e0t);
    egnn_main_kernel<<<NB * NN, THREADS, sizeof(SmemLayout)>>>(
        x, h, e0W, e0s,
        e1W, e1b, e1s, e1t,
        c0W, c0b, c0s, c0t,
        c1W, c1b, c1s, c1t,
        n0W, n0b, n0s, n0t,
        out);
}

// round 10
// speedup vs baseline: 1.2901x; 1.1884x over previous
#include <cuda_runtime.h>
#include <cuda_fp16.h>
#include <cstdint>

// EGNN layer: B=2, N=768, D=32, DM=64, K=16
#define NB 2
#define NN 768
#define DD 32
#define DMC 64
#define KNN 16
#define TJ 128
#define NTILES (NN / TJ)
#define THREADS 256

typedef unsigned int u32;
typedef unsigned long long u64;

// ---- fp16 split helpers: v = hi + lo, |lo| <= 2^-11 |v| ----
__device__ __forceinline__ void splitpair_h(float v0, float v1, u32& hi, u32& lo) {
    __half2 h = __floats2half2_rn(v0, v1);
    const float l0 = v0 - __low2float(h);
    const float l1 = v1 - __high2float(h);
    __half2 l = __floats2half2_rn(l0, l1);
    hi = *reinterpret_cast<u32*>(&h);
    lo = *reinterpret_cast<u32*>(&l);
}
__device__ __forceinline__ u32 packpair_h(float v0, float v1) {
    __half2 h = __floats2half2_rn(v0, v1);
    return *reinterpret_cast<u32*>(&h);
}

// m16n8k16 row.col f32.f16.f16.f32
__device__ __forceinline__ void mma16816(float* c, const u32* a, u32 b0, u32 b1) {
    asm volatile(
        "mma.sync.aligned.m16n8k16.row.col.f32.f16.f16.f32 "
        "{%0,%1,%2,%3}, {%4,%5,%6,%7}, {%8,%9}, {%0,%1,%2,%3};"
        : "+f"(c[0]), "+f"(c[1]), "+f"(c[2]), "+f"(c[3])
        : "r"(a[0]), "r"(a[1]), "r"(a[2]), "r"(a[3]), "r"(b0), "r"(b1));
}

// Per-node precomputed e0 partials (folded with BN affine)
__device__ float g_As[NB * NN * DMC];   // (h_j @ W_top) * s0
__device__ float g_Bs[NB * NN * DMC];   // (h_i @ W_mid + b0) * s0 + t0

__global__ void precompute_kernel(const float* __restrict__ h,
                                  const float* __restrict__ e0W,
                                  const float* __restrict__ e0b,
                                  const float* __restrict__ e0s,
                                  const float* __restrict__ e0t) {
    __shared__ float hv[DD];
    const int node = blockIdx.x;
    const int c = threadIdx.x;
    if (c < DD) hv[c] = h[node * DD + c];
    __syncthreads();
    float a1 = 0.f, a2 = 0.f;
#pragma unroll
    for (int d = 0; d < DD; d++) {
        const float hh = hv[d];
        a1 = fmaf(hh, e0W[d * DMC + c], a1);
        a2 = fmaf(hh, e0W[(DD + d) * DMC + c], a2);
    }
    const float s = e0s[c];
    g_As[node * DMC + c] = a1 * s;
    g_Bs[node * DMC + c] = (a2 + e0b[c]) * s + e0t[c];
}

// ---------------------------------------------------------------------------
// B-fragment smem (single fp16, paired-nt layout for LDS.128):
//   B[(ks*4 + (nt>>1))*64 + lane*2 + (nt&1)] = u64{ half2(k0,k0+1|n), half2(k0+8,k0+9|n) }
struct __align__(16) SmemLayout {
    u64 B1[1024];                // e1W folded fp16  (8KB)
    u64 B2[1024];                // c0W folded fp16  (8KB)
    float xs[NN * 3];
    float d2all[NN];
    float stage[KNN][DMC];       // f2 rows of selected neighbors
    float Bsi[DMC], wds[DMC], bias1[DMC], bias2[DMC], c1wf[DMC], mnode[DMC];
    int   slotmap[NN];
    float selval[KNN];
    float xsum[3];
    float redv[8];
    int   redi[8];
    int   seli[KNN];
};

__global__ void __launch_bounds__(THREADS, 3)
egnn_main_kernel(const float* __restrict__ x, const float* __restrict__ h,
                 const float* __restrict__ e0W, const float* __restrict__ e0s,
                 const float* __restrict__ e1W, const float* __restrict__ e1b,
                 const float* __restrict__ e1s, const float* __restrict__ e1t,
                 const float* __restrict__ c0W, const float* __restrict__ c0b,
                 const float* __restrict__ c0s, const float* __restrict__ c0t,
                 const float* __restrict__ c1W, const float* __restrict__ c1b,
                 const float* __restrict__ c1s, const float* __restrict__ c1t,
                 const float* __restrict__ n0W, const float* __restrict__ n0b,
                 const float* __restrict__ n0s, const float* __restrict__ n0t,
                 float* __restrict__ out) {
    extern __shared__ char smraw[];
    SmemLayout* sm = reinterpret_cast<SmemLayout*>(smraw);

    const int bi = blockIdx.x;
    const int b  = bi / NN;
    const int i  = bi - b * NN;
    const int t  = threadIdx.x;
    const int w  = t >> 5;
    const int lane = t & 31;
    const int g  = lane >> 2;
    const int tg = lane & 3;

    // ---- fold weights into paired per-lane fp16 B-fragment layout ----
    for (int e = t; e < 1024; e += THREADS) {
        const int l  = e & 31;
        const int nt = (e >> 5) & 7;
        const int ks = e >> 8;
        const int k0 = ks * 16 + 2 * (l & 3);
        const int n  = nt * 8 + (l >> 2);
        const int dst = (ks * 4 + (nt >> 1)) * 64 + l * 2 + (nt & 1);
        const float s1 = e1s[n], s2 = c0s[n];
        u32 a0 = packpair_h(e1W[k0 * DMC + n] * s1, e1W[(k0 + 1) * DMC + n] * s1);
        u32 a1 = packpair_h(e1W[(k0 + 8) * DMC + n] * s1, e1W[(k0 + 9) * DMC + n] * s1);
        sm->B1[dst] = (u64)a0 | ((u64)a1 << 32);
        a0 = packpair_h(c0W[k0 * DMC + n] * s2, c0W[(k0 + 1) * DMC + n] * s2);
        a1 = packpair_h(c0W[(k0 + 8) * DMC + n] * s2, c0W[(k0 + 9) * DMC + n] * s2);
        sm->B2[dst] = (u64)a0 | ((u64)a1 << 32);
    }
    if (t < DMC) {
        sm->bias1[t] = e1b[t] * e1s[t] + e1t[t];
        sm->bias2[t] = c0b[t] * c0s[t] + c0t[t];
        sm->Bsi[t]   = g_Bs[bi * DMC + t];
        sm->wds[t]   = e0W[2 * DD * DMC + t] * e0s[t];
        sm->c1wf[t]  = c1W[t] * c1s[0];
    }
    for (int e = t; e < NN * 3; e += THREADS) sm->xs[e] = x[b * NN * 3 + e];
    for (int e = t; e < NN; e += THREADS) sm->slotmap[e] = -1;
    if (t == 0) { sm->xsum[0] = 0.f; sm->xsum[1] = 0.f; sm->xsum[2] = 0.f; }
    const float c1bf = c1b[0] * c1s[0] + c1t[0];
    __syncthreads();

    const float xi0 = sm->xs[i * 3 + 0];
    const float xi1 = sm->xs[i * 3 + 1];
    const float xi2 = sm->xs[i * 3 + 2];

    // ---- distances ----
    for (int j = t; j < NN; j += THREADS) {
        const float dx = sm->xs[j * 3 + 0] - xi0;
        const float dy = sm->xs[j * 3 + 1] - xi1;
        const float dz = sm->xs[j * 3 + 2] - xi2;
        sm->d2all[j] = dx * dx + dy * dy + dz * dz;
    }
    __syncthreads();

    // ---- kNN: 16 sequential block argmins (tie-break lower index) ----
    const float INF = __int_as_float(0x7f800000);
    for (int s = 0; s < KNN; s++) {
        float bv = INF; int bidx = NN;
#pragma unroll
        for (int j = t; j < NN; j += THREADS) {
            const float v = sm->d2all[j];
            if (v < bv || (v == bv && j < bidx)) { bv = v; bidx = j; }
        }
#pragma unroll
        for (int off = 16; off; off >>= 1) {
            const float ov = __shfl_down_sync(0xffffffffu, bv, off);
            const int   oi = __shfl_down_sync(0xffffffffu, bidx, off);
            if (ov < bv || (ov == bv && oi < bidx)) { bv = ov; bidx = oi; }
        }
        if (lane == 0) { sm->redv[w] = bv; sm->redi[w] = bidx; }
        __syncthreads();
        if (t == 0) {
            float fv = sm->redv[0]; int fi = sm->redi[0];
#pragma unroll
            for (int q = 1; q < 8; q++) {
                const float wv = sm->redv[q]; const int wi = sm->redi[q];
                if (wv < fv || (wv == fv && wi < fi)) { fv = wv; fi = wi; }
            }
            sm->seli[s] = fi;
            sm->selval[s] = fv;
            sm->d2all[fi] = INF;
        }
        __syncthreads();
    }
    if (t < KNN) {
        sm->d2all[sm->seli[t]] = sm->selval[t];   // restore
        sm->slotmap[sm->seli[t]] = t;
    }
    __syncthreads();

    // ---- barrier-free mainloop: 8 warps x 16 rows, TJ=128 ----
    float xacc0 = 0.f, xacc1 = 0.f, xacc2 = 0.f;
    const float* As_b = g_As + (size_t)(b * NN) * DMC;

    for (int tile = 0; tile < NTILES; tile++) {
        const int j0 = tile * TJ;
        const int r0 = j0 + w * 16 + g;
        const int r1 = r0 + 8;
        const float d2a = sm->d2all[r0];
        const float d2b = sm->d2all[r1];
        const float* A0 = As_b + r0 * DMC;
        const float* A1 = As_b + r1 * DMC;

        // build A1-fragments in registers: f1 = relu(As + Bsi + d2*wds), fp16 split
        u32 ah[16], al[16];
#pragma unroll
        for (int ks = 0; ks < 4; ks++) {
            const int k0 = ks * 16 + 2 * tg;
            const float2 bs0 = *reinterpret_cast<const float2*>(&sm->Bsi[k0]);
            const float2 bs1 = *reinterpret_cast<const float2*>(&sm->Bsi[k0 + 8]);
            const float2 wd0 = *reinterpret_cast<const float2*>(&sm->wds[k0]);
            const float2 wd1 = *reinterpret_cast<const float2*>(&sm->wds[k0 + 8]);
            const float2 p0 = *reinterpret_cast<const float2*>(&A0[k0]);
            const float2 q0 = *reinterpret_cast<const float2*>(&A0[k0 + 8]);
            const float2 p1 = *reinterpret_cast<const float2*>(&A1[k0]);
            const float2 q1 = *reinterpret_cast<const float2*>(&A1[k0 + 8]);
            float v0 = fmaxf(fmaf(d2a, wd0.x, p0.x + bs0.x), 0.f);
            float v1 = fmaxf(fmaf(d2a, wd0.y, p0.y + bs0.y), 0.f);
            splitpair_h(v0, v1, ah[ks * 4 + 0], al[ks * 4 + 0]);
            v0 = fmaxf(fmaf(d2b, wd0.x, p1.x + bs0.x), 0.f);
            v1 = fmaxf(fmaf(d2b, wd0.y, p1.y + bs0.y), 0.f);
            splitpair_h(v0, v1, ah[ks * 4 + 1], al[ks * 4 + 1]);
            v0 = fmaxf(fmaf(d2a, wd1.x, q0.x + bs1.x), 0.f);
            v1 = fmaxf(fmaf(d2a, wd1.y, q0.y + bs1.y), 0.f);
            splitpair_h(v0, v1, ah[ks * 4 + 2], al[ks * 4 + 2]);
            v0 = fmaxf(fmaf(d2b, wd1.x, q1.x + bs1.x), 0.f);
            v1 = fmaxf(fmaf(d2b, wd1.y, q1.y + bs1.y), 0.f);
            splitpair_h(v0, v1, ah[ks * 4 + 3], al[ks * 4 + 3]);
        }

        const int slot0 = sm->slotmap[r0];
        const int slot1 = sm->slotmap[r1];
        u32 ah2[16], al2[16];

        // GEMM 1 in two N-halves; B via paired LDS.128, 2 MMAs (ah,al) per nt
#pragma unroll
        for (int hf = 0; hf < 2; hf++) {
            float acc[16];
#pragma unroll
            for (int q = 0; q < 16; q++) acc[q] = 0.f;
#pragma unroll
            for (int ks = 0; ks < 4; ks++) {
#pragma unroll
                for (int npl = 0; npl < 2; npl++) {
                    const int np = hf * 2 + npl;
                    const ulonglong2 b2 = *reinterpret_cast<const ulonglong2*>(
                        &sm->B1[(ks * 4 + np) * 64 + 2 * lane]);
#pragma unroll
                    for (int sub = 0; sub < 2; sub++) {
                        const u64 bb = sub ? b2.y : b2.x;
                        const u32 b0 = (u32)bb, b1 = (u32)(bb >> 32);
                        const int ntl = 2 * npl + sub;
                        mma16816(acc + ntl * 4, ah + ks * 4, b0, b1);
                        mma16816(acc + ntl * 4, al + ks * 4, b0, b1);
                    }
                }
            }
            // epilogue half: relu+bias, stage, re-split into A2 frags
#pragma unroll
            for (int ntl = 0; ntl < 4; ntl++) {
                const int nt = hf * 4 + ntl;
                const int n0 = nt * 8 + 2 * tg;
                const float2 bb = *reinterpret_cast<const float2*>(&sm->bias1[n0]);
                const float v0 = fmaxf(acc[ntl * 4 + 0] + bb.x, 0.f);
                const float v1 = fmaxf(acc[ntl * 4 + 1] + bb.y, 0.f);
                const float v2 = fmaxf(acc[ntl * 4 + 2] + bb.x, 0.f);
                const float v3 = fmaxf(acc[ntl * 4 + 3] + bb.y, 0.f);
                if (slot0 >= 0)
                    *reinterpret_cast<float2*>(&sm->stage[slot0][n0]) = make_float2(v0, v1);
                if (slot1 >= 0)
                    *reinterpret_cast<float2*>(&sm->stage[slot1][n0]) = make_float2(v2, v3);
                const int ks2 = nt >> 1, hh = (nt & 1) * 2;
                splitpair_h(v0, v1, ah2[ks2 * 4 + hh + 0], al2[ks2 * 4 + hh + 0]);
                splitpair_h(v2, v3, ah2[ks2 * 4 + hh + 1], al2[ks2 * 4 + hh + 1]);
            }
        }

        // GEMM 2 in two N-halves + c1 dot
        float dot0 = 0.f, dot1 = 0.f;
#pragma unroll
        for (int hf = 0; hf < 2; hf++) {
            float acc[16];
#pragma unroll
            for (int q = 0; q < 16; q++) acc[q] = 0.f;
#pragma unroll
            for (int ks = 0; ks < 4; ks++) {
#pragma unroll
                for (int npl = 0; npl < 2; npl++) {
                    const int np = hf * 2 + npl;
                    const ulonglong2 b2 = *reinterpret_cast<const ulonglong2*>(
                        &sm->B2[(ks * 4 + np) * 64 + 2 * lane]);
#pragma unroll
                    for (int sub = 0; sub < 2; sub++) {
                        const u64 bb = sub ? b2.y : b2.x;
                        const u32 b0 = (u32)bb, b1 = (u32)(bb >> 32);
                        const int ntl = 2 * npl + sub;
                        mma16816(acc + ntl * 4, ah2 + ks * 4, b0, b1);
                        mma16816(acc + ntl * 4, al2 + ks * 4, b0, b1);
                    }
                }
            }
#pragma unroll
            for (int ntl = 0; ntl < 4; ntl++) {
                const int nt = hf * 4 + ntl;
                const int n0 = nt * 8 + 2 * tg;
                const float2 bb = *reinterpret_cast<const float2*>(&sm->bias2[n0]);
                const float2 cw = *reinterpret_cast<const float2*>(&sm->c1wf[n0]);
                const float v0 = fmaxf(acc[ntl * 4 + 0] + bb.x, 0.f);
                const float v1 = fmaxf(acc[ntl * 4 + 1] + bb.y, 0.f);
                const float v2 = fmaxf(acc[ntl * 4 + 2] + bb.x, 0.f);
                const float v3 = fmaxf(acc[ntl * 4 + 3] + bb.y, 0.f);
                dot0 = fmaf(v0, cw.x, fmaf(v1, cw.y, dot0));
                dot1 = fmaf(v2, cw.x, fmaf(v3, cw.y, dot1));
            }
        }
        dot0 += __shfl_xor_sync(0xffffffffu, dot0, 1);
        dot0 += __shfl_xor_sync(0xffffffffu, dot0, 2);
        dot1 += __shfl_xor_sync(0xffffffffu, dot1, 1);
        dot1 += __shfl_xor_sync(0xffffffffu, dot1, 2);
        if (tg == 0) {
            const float w0 = fmaxf(dot0 + c1bf, 0.f);
            const float w1 = fmaxf(dot1 + c1bf, 0.f);
            xacc0 += w0 * (sm->xs[r0 * 3 + 0] - xi0) + w1 * (sm->xs[r1 * 3 + 0] - xi0);
            xacc1 += w0 * (sm->xs[r0 * 3 + 1] - xi1) + w1 * (sm->xs[r1 * 3 + 1] - xi1);
            xacc2 += w0 * (sm->xs[r0 * 3 + 2] - xi2) + w1 * (sm->xs[r1 * 3 + 2] - xi2);
        }
    }

    // ---- reduce coordinate update ----
#pragma unroll
    for (int off = 16; off; off >>= 1) {
        xacc0 += __shfl_down_sync(0xffffffffu, xacc0, off);
        xacc1 += __shfl_down_sync(0xffffffffu, xacc1, off);
        xacc2 += __shfl_down_sync(0xffffffffu, xacc2, off);
    }
    if (lane == 0) {
        atomicAdd(&sm->xsum[0], xacc0);
        atomicAdd(&sm->xsum[1], xacc1);
        atomicAdd(&sm->xsum[2], xacc2);
    }
    __syncthreads();   // stage + xsum complete

    // ---- m_node from staged rows ----
    if (t < DMC) {
        float m = 0.f;
#pragma unroll
        for (int s = 0; s < KNN; s++) m += sm->stage[s][t];
        sm->mnode[t] = m;
    }
    __syncthreads();

    // ---- outputs ----
    if (t < 3) out[bi * 3 + t] = sm->xs[i * 3 + t] + sm->xsum[t];
    if (t < DD) {
        float acc = 0.f;
        const float* hrow = h + bi * DD;
#pragma unroll
        for (int k = 0; k < DD; k++) acc = fmaf(hrow[k], n0W[k * DD + t], acc);
#pragma unroll
        for (int k = 0; k < DMC; k++) acc = fmaf(sm->mnode[k], n0W[(DD + k) * DD + t], acc);
        const float v = (acc + n0b[t]) * n0s[t] + n0t[t];
        out[NB * NN * 3 + bi * DD + t] = fmaxf(v, 0.f);
    }
}

// ---------------------------------------------------------------------------
extern "C" void kernel_launch(void* const* d_in, const int* in_sizes, int n_in,
                              void* d_out, int out_size) {
    const float* x   = (const float*)d_in[0];
    const float* h   = (const float*)d_in[1];
    const float* e0W = (const float*)d_in[2];
    const float* e0b = (const float*)d_in[3];
    const float* e0s = (const float*)d_in[4];
    const float* e0t = (const float*)d_in[5];
    const float* e1W = (const float*)d_in[6];
    const float* e1b = (const float*)d_in[7];
    const float* e1s = (const float*)d_in[8];
    const float* e1t = (const float*)d_in[9];
    const float* c0W = (const float*)d_in[10];
    const float* c0b = (const float*)d_in[11];
    const float* c0s = (const float*)d_in[12];
    const float* c0t = (const float*)d_in[13];
    const float* c1W = (const float*)d_in[14];
    const float* c1b = (const float*)d_in[15];
    const float* c1s = (const float*)d_in[16];
    const float* c1t = (const float*)d_in[17];
    const float* n0W = (const float*)d_in[18];
    const float* n0b = (const float*)d_in[19];
    const float* n0s = (const float*)d_in[20];
    const float* n0t = (const float*)d_in[21];
    float* out = (float*)d_out;

    static_assert(sizeof(SmemLayout) < 76 * 1024, "smem too big for 3 CTAs");
    cudaFuncSetAttribute(egnn_main_kernel,
                         cudaFuncAttributeMaxDynamicSharedMemorySize,
                         (int)sizeof(SmemLayout));

    precompute_kernel<<<NB * NN, 64>>>(h, e0W, e0b, e0s, e0t);
    egnn_main_kernel<<<NB * NN, THREADS, sizeof(SmemLayout)>>>(
        x, h, e0W, e0s,
        e1W, e1b, e1s, e1t,
        c0W, c0b, c0s, c0t,
        c1W, c1b, c1s, c1t,
        n0W, n0b, n0s, n0t,
        out);
}

// round 14
// speedup vs baseline: 1.4736x; 1.1422x over previous
#include <cuda_runtime.h>
#include <cuda_fp16.h>
#include <cstdint>

// EGNN layer: B=2, N=768, D=32, DM=64, K=16
#define NB 2
#define NN 768
#define DD 32
#define DMC 64
#define KNN 16
#define TJ 128
#define NTILES (NN / TJ)
#define THREADS 256
#define NRB (NN / 16)            // 48 row-blocks per batch

typedef unsigned int u32;
typedef unsigned long long u64;

// ---- fp16 split helpers: v = hi + lo, |lo| <= 2^-11 |v| ----
__device__ __forceinline__ void splitpair_h(float v0, float v1, u32& hi, u32& lo) {
    __half2 h = __floats2half2_rn(v0, v1);
    const float l0 = v0 - __low2float(h);
    const float l1 = v1 - __high2float(h);
    __half2 l = __floats2half2_rn(l0, l1);
    hi = *reinterpret_cast<u32*>(&h);
    lo = *reinterpret_cast<u32*>(&l);
}
__device__ __forceinline__ u32 packpair_h(float v0, float v1) {
    __half2 h = __floats2half2_rn(v0, v1);
    return *reinterpret_cast<u32*>(&h);
}

// m16n8k16 row.col f32.f16.f16.f32
__device__ __forceinline__ void mma16816(float* c, const u32* a, u32 b0, u32 b1) {
    asm volatile(
        "mma.sync.aligned.m16n8k16.row.col.f32.f16.f16.f32 "
        "{%0,%1,%2,%3}, {%4,%5,%6,%7}, {%8,%9}, {%0,%1,%2,%3};"
        : "+f"(c[0]), "+f"(c[1]), "+f"(c[2]), "+f"(c[3])
        : "r"(a[0]), "r"(a[1]), "r"(a[2]), "r"(a[3]), "r"(b0), "r"(b1));
}

// Per-node precomputed e0 partials (folded with BN affine)
// g_As2: fragment-order layout. For (b, R=row-block, ks, e in {k0 | k0+8}):
//   float4 slab[32 lanes]; lane = 4*g + tg holds
//   { As[R*16+g][k0], As[R*16+g][k0+1], As[R*16+8+g][k0], As[R*16+8+g][k0+1] }
//   with k0 = ks*16 + 2*tg + 8*e.  Mainloop reads 2 coalesced LDG.128 per ks.
__device__ float4 g_As2[NB * NRB * 8 * 32];
__device__ float  g_Bs[NB * NN * DMC];   // (h_i @ W_mid + b0) * s0 + t0

__global__ void precompute_kernel(const float* __restrict__ h,
                                  const float* __restrict__ e0W,
                                  const float* __restrict__ e0b,
                                  const float* __restrict__ e0s,
                                  const float* __restrict__ e0t) {
    __shared__ float hv[DD];
    const int node = blockIdx.x;          // b*NN + n
    const int c = threadIdx.x;            // 0..63
    if (c < DD) hv[c] = h[node * DD + c];
    __syncthreads();
    float a1 = 0.f, a2 = 0.f;
#pragma unroll
    for (int d = 0; d < DD; d++) {
        const float hh = hv[d];
        a1 = fmaf(hh, e0W[d * DMC + c], a1);
        a2 = fmaf(hh, e0W[(DD + d) * DMC + c], a2);
    }
    const float s = e0s[c];
    // scatter As into fragment layout
    const int b = node / NN;
    const int n = node - b * NN;
    const int R = n >> 4;
    const int rl = n & 15;
    const int g = rl & 7;
    const int hiRow = rl >> 3;            // 0 -> (x,y) slot, 1 -> (z,w) slot
    const int ks = c >> 4;
    const int rem = c & 15;
    const int e = rem >> 3;
    const int tg = (rem >> 1) & 3;
    const int p = rem & 1;
    const int lane = 4 * g + tg;
    float* dst = reinterpret_cast<float*>(
        &g_As2[((b * NRB + R) * 8 + ks * 2 + e) * 32 + lane]);
    dst[hiRow * 2 + p] = a1 * s;
    g_Bs[node * DMC + c] = (a2 + e0b[c]) * s + e0t[c];
}

// ---------------------------------------------------------------------------
// B-fragment smem (single fp16, paired-nt layout for LDS.128):
//   B[(ks*4 + (nt>>1))*64 + lane*2 + (nt&1)] = u64{ half2(k0,k0+1|n), half2(k0+8,k0+9|n) }
struct __align__(16) SmemLayout {
    u64 B1[1024];                // e1W folded fp16  (8KB)
    u64 B2[1024];                // c0W folded fp16  (8KB)
    float xs[NN * 3];
    float d2all[NN];
    float stage[KNN][DMC];       // f2 rows of selected neighbors
    float Bsi[DMC], wds[DMC], bias1[DMC], bias2[DMC], c1wf[DMC], mnode[DMC];
    int   slotmap[NN];
    float selval[KNN];
    float xsum[3];
    float redv[8];
    int   redi[8];
    int   seli[KNN];
};

__global__ void __launch_bounds__(THREADS, 3)
egnn_main_kernel(const float* __restrict__ x, const float* __restrict__ h,
                 const float* __restrict__ e0W, const float* __restrict__ e0s,
                 const float* __restrict__ e1W, const float* __restrict__ e1b,
                 const float* __restrict__ e1s, const float* __restrict__ e1t,
                 const float* __restrict__ c0W, const float* __restrict__ c0b,
                 const float* __restrict__ c0s, const float* __restrict__ c0t,
                 const float* __restrict__ c1W, const float* __restrict__ c1b,
                 const float* __restrict__ c1s, const float* __restrict__ c1t,
                 const float* __restrict__ n0W, const float* __restrict__ n0b,
                 const float* __restrict__ n0s, const float* __restrict__ n0t,
                 float* __restrict__ out) {
    extern __shared__ char smraw[];
    SmemLayout* sm = reinterpret_cast<SmemLayout*>(smraw);

    const int bi = blockIdx.x;
    const int b  = bi / NN;
    const int i  = bi - b * NN;
    const int t  = threadIdx.x;
    const int w  = t >> 5;
    const int lane = t & 31;
    const int g  = lane >> 2;
    const int tg = lane & 3;

    // ---- fold weights into paired per-lane fp16 B-fragment layout ----
    for (int e = t; e < 1024; e += THREADS) {
        const int l  = e & 31;
        const int nt = (e >> 5) & 7;
        const int ks = e >> 8;
        const int k0 = ks * 16 + 2 * (l & 3);
        const int n  = nt * 8 + (l >> 2);
        const int dst = (ks * 4 + (nt >> 1)) * 64 + l * 2 + (nt & 1);
        const float s1 = e1s[n], s2 = c0s[n];
        u32 a0 = packpair_h(e1W[k0 * DMC + n] * s1, e1W[(k0 + 1) * DMC + n] * s1);
        u32 a1 = packpair_h(e1W[(k0 + 8) * DMC + n] * s1, e1W[(k0 + 9) * DMC + n] * s1);
        sm->B1[dst] = (u64)a0 | ((u64)a1 << 32);
        a0 = packpair_h(c0W[k0 * DMC + n] * s2, c0W[(k0 + 1) * DMC + n] * s2);
        a1 = packpair_h(c0W[(k0 + 8) * DMC + n] * s2, c0W[(k0 + 9) * DMC + n] * s2);
        sm->B2[dst] = (u64)a0 | ((u64)a1 << 32);
    }
    if (t < DMC) {
        sm->bias1[t] = e1b[t] * e1s[t] + e1t[t];
        sm->bias2[t] = c0b[t] * c0s[t] + c0t[t];
        sm->Bsi[t]   = g_Bs[bi * DMC + t];
        sm->wds[t]   = e0W[2 * DD * DMC + t] * e0s[t];
        sm->c1wf[t]  = c1W[t] * c1s[0];
    }
    for (int e = t; e < NN * 3; e += THREADS) sm->xs[e] = x[b * NN * 3 + e];
    for (int e = t; e < NN; e += THREADS) sm->slotmap[e] = -1;
    if (t == 0) { sm->xsum[0] = 0.f; sm->xsum[1] = 0.f; sm->xsum[2] = 0.f; }
    const float c1bf = c1b[0] * c1s[0] + c1t[0];
    __syncthreads();

    const float xi0 = sm->xs[i * 3 + 0];
    const float xi1 = sm->xs[i * 3 + 1];
    const float xi2 = sm->xs[i * 3 + 2];

    // ---- distances ----
    for (int j = t; j < NN; j += THREADS) {
        const float dx = sm->xs[j * 3 + 0] - xi0;
        const float dy = sm->xs[j * 3 + 1] - xi1;
        const float dz = sm->xs[j * 3 + 2] - xi2;
        sm->d2all[j] = dx * dx + dy * dy + dz * dz;
    }
    __syncthreads();

    // ---- kNN: 16 sequential block argmins (tie-break lower index) ----
    const float INF = __int_as_float(0x7f800000);
    for (int s = 0; s < KNN; s++) {
        float bv = INF; int bidx = NN;
#pragma unroll
        for (int j = t; j < NN; j += THREADS) {
            const float v = sm->d2all[j];
            if (v < bv || (v == bv && j < bidx)) { bv = v; bidx = j; }
        }
#pragma unroll
        for (int off = 16; off; off >>= 1) {
            const float ov = __shfl_down_sync(0xffffffffu, bv, off);
            const int   oi = __shfl_down_sync(0xffffffffu, bidx, off);
            if (ov < bv || (ov == bv && oi < bidx)) { bv = ov; bidx = oi; }
        }
        if (lane == 0) { sm->redv[w] = bv; sm->redi[w] = bidx; }
        __syncthreads();
        if (t == 0) {
            float fv = sm->redv[0]; int fi = sm->redi[0];
#pragma unroll
            for (int q = 1; q < 8; q++) {
                const float wv = sm->redv[q]; const int wi = sm->redi[q];
                if (wv < fv || (wv == fv && wi < fi)) { fv = wv; fi = wi; }
            }
            sm->seli[s] = fi;
            sm->selval[s] = fv;
            sm->d2all[fi] = INF;
        }
        __syncthreads();
    }
    if (t < KNN) {
        sm->d2all[sm->seli[t]] = sm->selval[t];   // restore
        sm->slotmap[sm->seli[t]] = t;
    }
    __syncthreads();

    // ---- barrier-free mainloop: 8 warps x 16 rows, TJ=128 ----
    float xacc0 = 0.f, xacc1 = 0.f, xacc2 = 0.f;

    for (int tile = 0; tile < NTILES; tile++) {
        const int j0 = tile * TJ;
        const int r0 = j0 + w * 16 + g;
        const int r1 = r0 + 8;
        const float d2a = sm->d2all[r0];
        const float d2b = sm->d2all[r1];
        // fragment-layout A base for this warp's 16-row block
        const float4* Afrag = &g_As2[((b * NRB + tile * 8 + w) * 8) * 32 + lane];

        // build A1-fragments in registers: f1 = relu(As + Bsi + d2*wds), fp16 split
        u32 ah[16], al[16];
#pragma unroll
        for (int ks = 0; ks < 4; ks++) {
            const int k0 = ks * 16 + 2 * tg;
            const float2 bs0 = *reinterpret_cast<const float2*>(&sm->Bsi[k0]);
            const float2 bs1 = *reinterpret_cast<const float2*>(&sm->Bsi[k0 + 8]);
            const float2 wd0 = *reinterpret_cast<const float2*>(&sm->wds[k0]);
            const float2 wd1 = *reinterpret_cast<const float2*>(&sm->wds[k0 + 8]);
            const float4 fa = Afrag[(ks * 2 + 0) * 32];   // rows r0,r1 @ k0,k0+1
            const float4 fb = Afrag[(ks * 2 + 1) * 32];   // rows r0,r1 @ k0+8,k0+9
            float v0 = fmaxf(fmaf(d2a, wd0.x, fa.x + bs0.x), 0.f);
            float v1 = fmaxf(fmaf(d2a, wd0.y, fa.y + bs0.y), 0.f);
            splitpair_h(v0, v1, ah[ks * 4 + 0], al[ks * 4 + 0]);
            v0 = fmaxf(fmaf(d2b, wd0.x, fa.z + bs0.x), 0.f);
            v1 = fmaxf(fmaf(d2b, wd0.y, fa.w + bs0.y), 0.f);
            splitpair_h(v0, v1, ah[ks * 4 + 1], al[ks * 4 + 1]);
            v0 = fmaxf(fmaf(d2a, wd1.x, fb.x + bs1.x), 0.f);
            v1 = fmaxf(fmaf(d2a, wd1.y, fb.y + bs1.y), 0.f);
            splitpair_h(v0, v1, ah[ks * 4 + 2], al[ks * 4 + 2]);
            v0 = fmaxf(fmaf(d2b, wd1.x, fb.z + bs1.x), 0.f);
            v1 = fmaxf(fmaf(d2b, wd1.y, fb.w + bs1.y), 0.f);
            splitpair_h(v0, v1, ah[ks * 4 + 3], al[ks * 4 + 3]);
        }

        const int slot0 = sm->slotmap[r0];
        const int slot1 = sm->slotmap[r1];
        u32 ah2[16], al2[16];

        // GEMM 1 in two N-halves; B via paired LDS.128, 2 MMAs (ah,al) per nt
#pragma unroll
        for (int hf = 0; hf < 2; hf++) {
            float acc[16];
#pragma unroll
            for (int q = 0; q < 16; q++) acc[q] = 0.f;
#pragma unroll
            for (int ks = 0; ks < 4; ks++) {
#pragma unroll
                for (int npl = 0; npl < 2; npl++) {
                    const int np = hf * 2 + npl;
                    const ulonglong2 b2 = *reinterpret_cast<const ulonglong2*>(
                        &sm->B1[(ks * 4 + np) * 64 + 2 * lane]);
#pragma unroll
                    for (int sub = 0; sub < 2; sub++) {
                        const u64 bb = sub ? b2.y : b2.x;
                        const u32 b0 = (u32)bb, b1 = (u32)(bb >> 32);
                        const int ntl = 2 * npl + sub;
                        mma16816(acc + ntl * 4, ah + ks * 4, b0, b1);
                        mma16816(acc + ntl * 4, al + ks * 4, b0, b1);
                    }
                }
            }
            // epilogue half: relu+bias, stage, re-split into A2 frags
#pragma unroll
            for (int ntl = 0; ntl < 4; ntl++) {
                const int nt = hf * 4 + ntl;
                const int n0 = nt * 8 + 2 * tg;
                const float2 bb = *reinterpret_cast<const float2*>(&sm->bias1[n0]);
                const float v0 = fmaxf(acc[ntl * 4 + 0] + bb.x, 0.f);
                const float v1 = fmaxf(acc[ntl * 4 + 1] + bb.y, 0.f);
                const float v2 = fmaxf(acc[ntl * 4 + 2] + bb.x, 0.f);
                const float v3 = fmaxf(acc[ntl * 4 + 3] + bb.y, 0.f);
                if (slot0 >= 0)
                    *reinterpret_cast<float2*>(&sm->stage[slot0][n0]) = make_float2(v0, v1);
                if (slot1 >= 0)
                    *reinterpret_cast<float2*>(&sm->stage[slot1][n0]) = make_float2(v2, v3);
                const int ks2 = nt >> 1, hh = (nt & 1) * 2;
                splitpair_h(v0, v1, ah2[ks2 * 4 + hh + 0], al2[ks2 * 4 + hh + 0]);
                splitpair_h(v2, v3, ah2[ks2 * 4 + hh + 1], al2[ks2 * 4 + hh + 1]);
            }
        }

        // GEMM 2 in two N-halves + c1 dot
        float dot0 = 0.f, dot1 = 0.f;
#pragma unroll
        for (int hf = 0; hf < 2; hf++) {
            float acc[16];
#pragma unroll
            for (int q = 0; q < 16; q++) acc[q] = 0.f;
#pragma unroll
            for (int ks = 0; ks < 4; ks++) {
#pragma unroll
                for (int npl = 0; npl < 2; npl++) {
                    const int np = hf * 2 + npl;
                    const ulonglong2 b2 = *reinterpret_cast<const ulonglong2*>(
                        &sm->B2[(ks * 4 + np) * 64 + 2 * lane]);
#pragma unroll
                    for (int sub = 0; sub < 2; sub++) {
                        const u64 bb = sub ? b2.y : b2.x;
                        const u32 b0 = (u32)bb, b1 = (u32)(bb >> 32);
                        const int ntl = 2 * npl + sub;
                        mma16816(acc + ntl * 4, ah2 + ks * 4, b0, b1);
                        mma16816(acc + ntl * 4, al2 + ks * 4, b0, b1);
                    }
                }
            }
#pragma unroll
            for (int ntl = 0; ntl < 4; ntl++) {
                const int nt = hf * 4 + ntl;
                const int n0 = nt * 8 + 2 * tg;
                const float2 bb = *reinterpret_cast<const float2*>(&sm->bias2[n0]);
                const float2 cw = *reinterpret_cast<const float2*>(&sm->c1wf[n0]);
                const float v0 = fmaxf(acc[ntl * 4 + 0] + bb.x, 0.f);
                const float v1 = fmaxf(acc[ntl * 4 + 1] + bb.y, 0.f);
                const float v2 = fmaxf(acc[ntl * 4 + 2] + bb.x, 0.f);
                const float v3 = fmaxf(acc[ntl * 4 + 3] + bb.y, 0.f);
                dot0 = fmaf(v0, cw.x, fmaf(v1, cw.y, dot0));
                dot1 = fmaf(v2, cw.x, fmaf(v3, cw.y, dot1));
            }
        }
        dot0 += __shfl_xor_sync(0xffffffffu, dot0, 1);
        dot0 += __shfl_xor_sync(0xffffffffu, dot0, 2);
        dot1 += __shfl_xor_sync(0xffffffffu, dot1, 1);
        dot1 += __shfl_xor_sync(0xffffffffu, dot1, 2);
        if (tg == 0) {
            const float w0 = fmaxf(dot0 + c1bf, 0.f);
            const float w1 = fmaxf(dot1 + c1bf, 0.f);
            xacc0 += w0 * (sm->xs[r0 * 3 + 0] - xi0) + w1 * (sm->xs[r1 * 3 + 0] - xi0);
            xacc1 += w0 * (sm->xs[r0 * 3 + 1] - xi1) + w1 * (sm->xs[r1 * 3 + 1] - xi1);
            xacc2 += w0 * (sm->xs[r0 * 3 + 2] - xi2) + w1 * (sm->xs[r1 * 3 + 2] - xi2);
        }
    }

    // ---- reduce coordinate update ----
#pragma unroll
    for (int off = 16; off; off >>= 1) {
        xacc0 += __shfl_down_sync(0xffffffffu, xacc0, off);
        xacc1 += __shfl_down_sync(0xffffffffu, xacc1, off);
        xacc2 += __shfl_down_sync(0xffffffffu, xacc2, off);
    }
    if (lane == 0) {
        atomicAdd(&sm->xsum[0], xacc0);
        atomicAdd(&sm->xsum[1], xacc1);
        atomicAdd(&sm->xsum[2], xacc2);
    }
    __syncthreads();   // stage + xsum complete

    // ---- m_node from staged rows ----
    if (t < DMC) {
        float m = 0.f;
#pragma unroll
        for (int s = 0; s < KNN; s++) m += sm->stage[s][t];
        sm->mnode[t] = m;
    }
    __syncthreads();

    // ---- outputs ----
    if (t < 3) out[bi * 3 + t] = sm->xs[i * 3 + t] + sm->xsum[t];
    if (t < DD) {
        float acc = 0.f;
        const float* hrow = h + bi * DD;
#pragma unroll
        for (int k = 0; k < DD; k++) acc = fmaf(hrow[k], n0W[k * DD + t], acc);
#pragma unroll
        for (int k = 0; k < DMC; k++) acc = fmaf(sm->mnode[k], n0W[(DD + k) * DD + t], acc);
        const float v = (acc + n0b[t]) * n0s[t] + n0t[t];
        out[NB * NN * 3 + bi * DD + t] = fmaxf(v, 0.f);
    }
}

// ---------------------------------------------------------------------------
extern "C" void kernel_launch(void* const* d_in, const int* in_sizes, int n_in,
                              void* d_out, int out_size) {
    const float* x   = (const float*)d_in[0];
    const float* h   = (const float*)d_in[1];
    const float* e0W = (const float*)d_in[2];
    const float* e0b = (const float*)d_in[3];
    const float* e0s = (const float*)d_in[4];
    const float* e0t = (const float*)d_in[5];
    const float* e1W = (const float*)d_in[6];
    const float* e1b = (const float*)d_in[7];
    const float* e1s = (const float*)d_in[8];
    const float* e1t = (const float*)d_in[9];
    const float* c0W = (const float*)d_in[10];
    const float* c0b = (const float*)d_in[11];
    const float* c0s = (const float*)d_in[12];
    const float* c0t = (const float*)d_in[13];
    const float* c1W = (const float*)d_in[14];
    const float* c1b = (const float*)d_in[15];
    const float* c1s = (const float*)d_in[16];
    const float* c1t = (const float*)d_in[17];
    const float* n0W = (const float*)d_in[18];
    const float* n0b = (const float*)d_in[19];
    const float* n0s = (const float*)d_in[20];
    const float* n0t = (const float*)d_in[21];
    float* out = (float*)d_out;

    static_assert(sizeof(SmemLayout) < 76 * 1024, "smem too big for 3 CTAs");
    cudaFuncSetAttribute(egnn_main_kernel,
                         cudaFuncAttributeMaxDynamicSharedMemorySize,
                         (int)sizeof(SmemLayout));

    precompute_kernel<<<NB * NN, 64>>>(h, e0W, e0b, e0s, e0t);
    egnn_main_kernel<<<NB * NN, THREADS, sizeof(SmemLayout)>>>(
        x, h, e0W, e0s,
        e1W, e1b, e1s, e1t,
        c0W, c0b, c0s, c0t,
        c1W, c1b, c1s, c1t,
        n0W, n0b, n0s, n0t,
        out);
}

// round 15
// speedup vs baseline: 1.6712x; 1.1341x over previous
#include <cuda_runtime.h>
#include <cuda_fp16.h>
#include <cstdint>

// EGNN layer: B=2, N=768, D=32, DM=64, K=16
#define NB 2
#define NN 768
#define DD 32
#define DMC 64
#define KNN 16
#define TJ 128
#define NTILES (NN / TJ)
#define THREADS 256
#define NRB (NN / 16)            // 48 row-blocks per batch

typedef unsigned int u32;
typedef unsigned long long u64;

// ---- fp16 split helpers: v = hi + lo, |lo| <= 2^-11 |v| ----
__device__ __forceinline__ void splitpair_h(float v0, float v1, u32& hi, u32& lo) {
    __half2 h = __floats2half2_rn(v0, v1);
    const float l0 = v0 - __low2float(h);
    const float l1 = v1 - __high2float(h);
    __half2 l = __floats2half2_rn(l0, l1);
    hi = *reinterpret_cast<u32*>(&h);
    lo = *reinterpret_cast<u32*>(&l);
}
__device__ __forceinline__ u32 packpair_h(float v0, float v1) {
    __half2 h = __floats2half2_rn(v0, v1);
    return *reinterpret_cast<u32*>(&h);
}

// m16n8k16 row.col f32.f16.f16.f32
__device__ __forceinline__ void mma16816(float* c, const u32* a, u32 b0, u32 b1) {
    asm volatile(
        "mma.sync.aligned.m16n8k16.row.col.f32.f16.f16.f32 "
        "{%0,%1,%2,%3}, {%4,%5,%6,%7}, {%8,%9}, {%0,%1,%2,%3};"
        : "+f"(c[0]), "+f"(c[1]), "+f"(c[2]), "+f"(c[3])
        : "r"(a[0]), "r"(a[1]), "r"(a[2]), "r"(a[3]), "r"(b0), "r"(b1));
}

// Per-node precomputed e0 partials (folded with BN affine)
// g_As2: fragment-order layout (see precompute scatter below).
__device__ float4 g_As2[NB * NRB * 8 * 32];
__device__ float  g_Bs[NB * NN * DMC];   // (h_i @ W_mid + b0) * s0 + t0

__global__ void precompute_kernel(const float* __restrict__ h,
                                  const float* __restrict__ e0W,
                                  const float* __restrict__ e0b,
                                  const float* __restrict__ e0s,
                                  const float* __restrict__ e0t) {
    __shared__ float hv[DD];
    const int node = blockIdx.x;          // b*NN + n
    const int c = threadIdx.x;            // 0..63
    if (c < DD) hv[c] = h[node * DD + c];
    __syncthreads();
    float a1 = 0.f, a2 = 0.f;
#pragma unroll
    for (int d = 0; d < DD; d++) {
        const float hh = hv[d];
        a1 = fmaf(hh, e0W[d * DMC + c], a1);
        a2 = fmaf(hh, e0W[(DD + d) * DMC + c], a2);
    }
    const float s = e0s[c];
    // scatter As into fragment layout
    const int b = node / NN;
    const int n = node - b * NN;
    const int R = n >> 4;
    const int rl = n & 15;
    const int g = rl & 7;
    const int hiRow = rl >> 3;            // 0 -> (x,y) slot, 1 -> (z,w) slot
    const int ks = c >> 4;
    const int rem = c & 15;
    const int e = rem >> 3;
    const int tg = (rem >> 1) & 3;
    const int p = rem & 1;
    const int lane = 4 * g + tg;
    float* dst = reinterpret_cast<float*>(
        &g_As2[((b * NRB + R) * 8 + ks * 2 + e) * 32 + lane]);
    dst[hiRow * 2 + p] = a1 * s;
    g_Bs[node * DMC + c] = (a2 + e0b[c]) * s + e0t[c];
}

// ---------------------------------------------------------------------------
// B-fragment smem (single fp16, paired-nt layout for LDS.128):
//   B[(ks*4 + (nt>>1))*64 + lane*2 + (nt&1)] = u64{ half2(k0,k0+1|n), half2(k0+8,k0+9|n) }
struct __align__(16) SmemLayout {
    u64 B1[1024];                // e1W folded fp16  (8KB)
    u64 B2[1024];                // c0W folded fp16  (8KB)
    float xs[NN * 3];
    float d2all[NN];
    float stage[KNN][DMC];       // f2 rows of selected neighbors
    float Bsi[DMC], wds[DMC], bias1[DMC], bias2[DMC], c1wf[DMC], mnode[DMC];
    int   slotmap[NN];
    float selval[KNN];
    float xsum[3];
    float redv[8];
    int   redi[8];
    int   seli[KNN];
};

__global__ void __launch_bounds__(THREADS, 3)
egnn_main_kernel(const float* __restrict__ x, const float* __restrict__ h,
                 const float* __restrict__ e0W, const float* __restrict__ e0s,
                 const float* __restrict__ e1W, const float* __restrict__ e1b,
                 const float* __restrict__ e1s, const float* __restrict__ e1t,
                 const float* __restrict__ c0W, const float* __restrict__ c0b,
                 const float* __restrict__ c0s, const float* __restrict__ c0t,
                 const float* __restrict__ c1W, const float* __restrict__ c1b,
                 const float* __restrict__ c1s, const float* __restrict__ c1t,
                 const float* __restrict__ n0W, const float* __restrict__ n0b,
                 const float* __restrict__ n0s, const float* __restrict__ n0t,
                 float* __restrict__ out) {
    extern __shared__ char smraw[];
    SmemLayout* sm = reinterpret_cast<SmemLayout*>(smraw);

    const int bi = blockIdx.x;
    const int b  = bi / NN;
    const int i  = bi - b * NN;
    const int t  = threadIdx.x;
    const int w  = t >> 5;
    const int lane = t & 31;
    const int g  = lane >> 2;
    const int tg = lane & 3;

    // ---- fold weights into paired per-lane fp16 B-fragment layout ----
    for (int e = t; e < 1024; e += THREADS) {
        const int l  = e & 31;
        const int nt = (e >> 5) & 7;
        const int ks = e >> 8;
        const int k0 = ks * 16 + 2 * (l & 3);
        const int n  = nt * 8 + (l >> 2);
        const int dst = (ks * 4 + (nt >> 1)) * 64 + l * 2 + (nt & 1);
        const float s1 = e1s[n], s2 = c0s[n];
        u32 a0 = packpair_h(e1W[k0 * DMC + n] * s1, e1W[(k0 + 1) * DMC + n] * s1);
        u32 a1 = packpair_h(e1W[(k0 + 8) * DMC + n] * s1, e1W[(k0 + 9) * DMC + n] * s1);
        sm->B1[dst] = (u64)a0 | ((u64)a1 << 32);
        a0 = packpair_h(c0W[k0 * DMC + n] * s2, c0W[(k0 + 1) * DMC + n] * s2);
        a1 = packpair_h(c0W[(k0 + 8) * DMC + n] * s2, c0W[(k0 + 9) * DMC + n] * s2);
        sm->B2[dst] = (u64)a0 | ((u64)a1 << 32);
    }
    if (t < DMC) {
        sm->bias1[t] = e1b[t] * e1s[t] + e1t[t];
        sm->bias2[t] = c0b[t] * c0s[t] + c0t[t];
        sm->Bsi[t]   = g_Bs[bi * DMC + t];
        sm->wds[t]   = e0W[2 * DD * DMC + t] * e0s[t];
        sm->c1wf[t]  = c1W[t] * c1s[0];
    }
    for (int e = t; e < NN * 3; e += THREADS) sm->xs[e] = x[b * NN * 3 + e];
    for (int e = t; e < NN; e += THREADS) sm->slotmap[e] = -1;
    if (t == 0) { sm->xsum[0] = 0.f; sm->xsum[1] = 0.f; sm->xsum[2] = 0.f; }
    const float c1bf = c1b[0] * c1s[0] + c1t[0];
    __syncthreads();

    const float xi0 = sm->xs[i * 3 + 0];
    const float xi1 = sm->xs[i * 3 + 1];
    const float xi2 = sm->xs[i * 3 + 2];

    // ---- distances ----
    for (int j = t; j < NN; j += THREADS) {
        const float dx = sm->xs[j * 3 + 0] - xi0;
        const float dy = sm->xs[j * 3 + 1] - xi1;
        const float dz = sm->xs[j * 3 + 2] - xi2;
        sm->d2all[j] = dx * dx + dy * dy + dz * dz;
    }
    __syncthreads();

    // ---- kNN: 16 sequential block argmins (tie-break lower index) ----
    const float INF = __int_as_float(0x7f800000);
    for (int s = 0; s < KNN; s++) {
        float bv = INF; int bidx = NN;
#pragma unroll
        for (int j = t; j < NN; j += THREADS) {
            const float v = sm->d2all[j];
            if (v < bv || (v == bv && j < bidx)) { bv = v; bidx = j; }
        }
#pragma unroll
        for (int off = 16; off; off >>= 1) {
            const float ov = __shfl_down_sync(0xffffffffu, bv, off);
            const int   oi = __shfl_down_sync(0xffffffffu, bidx, off);
            if (ov < bv || (ov == bv && oi < bidx)) { bv = ov; bidx = oi; }
        }
        if (lane == 0) { sm->redv[w] = bv; sm->redi[w] = bidx; }
        __syncthreads();
        if (t == 0) {
            float fv = sm->redv[0]; int fi = sm->redi[0];
#pragma unroll
            for (int q = 1; q < 8; q++) {
                const float wv = sm->redv[q]; const int wi = sm->redi[q];
                if (wv < fv || (wv == fv && wi < fi)) { fv = wv; fi = wi; }
            }
            sm->seli[s] = fi;
            sm->selval[s] = fv;
            sm->d2all[fi] = INF;
        }
        __syncthreads();
    }
    if (t < KNN) {
        sm->d2all[sm->seli[t]] = sm->selval[t];   // restore
        sm->slotmap[sm->seli[t]] = t;
    }
    __syncthreads();

    // ---- barrier-free mainloop: 8 warps x 16 rows, TJ=128 ----
    float xacc0 = 0.f, xacc1 = 0.f, xacc2 = 0.f;

    for (int tile = 0; tile < NTILES; tile++) {
        const int j0 = tile * TJ;
        const int r0 = j0 + w * 16 + g;
        const int r1 = r0 + 8;
        const float d2a = sm->d2all[r0];
        const float d2b = sm->d2all[r1];
        // fragment-layout A base for this warp's 16-row block
        const float4* Afrag = &g_As2[((b * NRB + tile * 8 + w) * 8) * 32 + lane];

        // build A1-fragments in registers: f1 = relu(As + Bsi + d2*wds), fp16 split
        u32 ah[16], al[16];
#pragma unroll
        for (int ks = 0; ks < 4; ks++) {
            const int k0 = ks * 16 + 2 * tg;
            const float2 bs0 = *reinterpret_cast<const float2*>(&sm->Bsi[k0]);
            const float2 bs1 = *reinterpret_cast<const float2*>(&sm->Bsi[k0 + 8]);
            const float2 wd0 = *reinterpret_cast<const float2*>(&sm->wds[k0]);
            const float2 wd1 = *reinterpret_cast<const float2*>(&sm->wds[k0 + 8]);
            const float4 fa = Afrag[(ks * 2 + 0) * 32];   // rows r0,r1 @ k0,k0+1
            const float4 fb = Afrag[(ks * 2 + 1) * 32];   // rows r0,r1 @ k0+8,k0+9
            float v0 = fmaxf(fmaf(d2a, wd0.x, fa.x + bs0.x), 0.f);
            float v1 = fmaxf(fmaf(d2a, wd0.y, fa.y + bs0.y), 0.f);
            splitpair_h(v0, v1, ah[ks * 4 + 0], al[ks * 4 + 0]);
            v0 = fmaxf(fmaf(d2b, wd0.x, fa.z + bs0.x), 0.f);
            v1 = fmaxf(fmaf(d2b, wd0.y, fa.w + bs0.y), 0.f);
            splitpair_h(v0, v1, ah[ks * 4 + 1], al[ks * 4 + 1]);
            v0 = fmaxf(fmaf(d2a, wd1.x, fb.x + bs1.x), 0.f);
            v1 = fmaxf(fmaf(d2a, wd1.y, fb.y + bs1.y), 0.f);
            splitpair_h(v0, v1, ah[ks * 4 + 2], al[ks * 4 + 2]);
            v0 = fmaxf(fmaf(d2b, wd1.x, fb.z + bs1.x), 0.f);
            v1 = fmaxf(fmaf(d2b, wd1.y, fb.w + bs1.y), 0.f);
            splitpair_h(v0, v1, ah[ks * 4 + 3], al[ks * 4 + 3]);
        }

        const int slot0 = sm->slotmap[r0];
        const int slot1 = sm->slotmap[r1];
        u32 ah2[16];                        // A2: single fp16 (B-rounding dominates)

        // GEMM 1 in two N-halves; B via paired LDS.128, 2 MMAs (ah,al) per nt
#pragma unroll
        for (int hf = 0; hf < 2; hf++) {
            float acc[16];
#pragma unroll
            for (int q = 0; q < 16; q++) acc[q] = 0.f;
#pragma unroll
            for (int ks = 0; ks < 4; ks++) {
#pragma unroll
                for (int npl = 0; npl < 2; npl++) {
                    const int np = hf * 2 + npl;
                    const ulonglong2 b2 = *reinterpret_cast<const ulonglong2*>(
                        &sm->B1[(ks * 4 + np) * 64 + 2 * lane]);
#pragma unroll
                    for (int sub = 0; sub < 2; sub++) {
                        const u64 bb = sub ? b2.y : b2.x;
                        const u32 b0 = (u32)bb, b1 = (u32)(bb >> 32);
                        const int ntl = 2 * npl + sub;
                        mma16816(acc + ntl * 4, ah + ks * 4, b0, b1);
                        mma16816(acc + ntl * 4, al + ks * 4, b0, b1);
                    }
                }
            }
            // epilogue half: relu+bias, stage, pack single-fp16 A2 frags
#pragma unroll
            for (int ntl = 0; ntl < 4; ntl++) {
                const int nt = hf * 4 + ntl;
                const int n0 = nt * 8 + 2 * tg;
                const float2 bb = *reinterpret_cast<const float2*>(&sm->bias1[n0]);
                const float v0 = fmaxf(acc[ntl * 4 + 0] + bb.x, 0.f);
                const float v1 = fmaxf(acc[ntl * 4 + 1] + bb.y, 0.f);
                const float v2 = fmaxf(acc[ntl * 4 + 2] + bb.x, 0.f);
                const float v3 = fmaxf(acc[ntl * 4 + 3] + bb.y, 0.f);
                if (slot0 >= 0)
                    *reinterpret_cast<float2*>(&sm->stage[slot0][n0]) = make_float2(v0, v1);
                if (slot1 >= 0)
                    *reinterpret_cast<float2*>(&sm->stage[slot1][n0]) = make_float2(v2, v3);
                const int ks2 = nt >> 1, hh = (nt & 1) * 2;
                ah2[ks2 * 4 + hh + 0] = packpair_h(v0, v1);
                ah2[ks2 * 4 + hh + 1] = packpair_h(v2, v3);
            }
        }

        // GEMM 2 in two N-halves + c1 dot (single-term A: 1 MMA per nt-sub)
        float dot0 = 0.f, dot1 = 0.f;
#pragma unroll
        for (int hf = 0; hf < 2; hf++) {
            float acc[16];
#pragma unroll
            for (int q = 0; q < 16; q++) acc[q] = 0.f;
#pragma unroll
            for (int ks = 0; ks < 4; ks++) {
#pragma unroll
                for (int npl = 0; npl < 2; npl++) {
                    const int np = hf * 2 + npl;
                    const ulonglong2 b2 = *reinterpret_cast<const ulonglong2*>(
                        &sm->B2[(ks * 4 + np) * 64 + 2 * lane]);
#pragma unroll
                    for (int sub = 0; sub < 2; sub++) {
                        const u64 bb = sub ? b2.y : b2.x;
                        const u32 b0 = (u32)bb, b1 = (u32)(bb >> 32);
                        const int ntl = 2 * npl + sub;
                        mma16816(acc + ntl * 4, ah2 + ks * 4, b0, b1);
                    }
                }
            }
#pragma unroll
            for (int ntl = 0; ntl < 4; ntl++) {
                const int nt = hf * 4 + ntl;
                const int n0 = nt * 8 + 2 * tg;
                const float2 bb = *reinterpret_cast<const float2*>(&sm->bias2[n0]);
                const float2 cw = *reinterpret_cast<const float2*>(&sm->c1wf[n0]);
                const float v0 = fmaxf(acc[ntl * 4 + 0] + bb.x, 0.f);
                const float v1 = fmaxf(acc[ntl * 4 + 1] + bb.y, 0.f);
                const float v2 = fmaxf(acc[ntl * 4 + 2] + bb.x, 0.f);
                const float v3 = fmaxf(acc[ntl * 4 + 3] + bb.y, 0.f);
                dot0 = fmaf(v0, cw.x, fmaf(v1, cw.y, dot0));
                dot1 = fmaf(v2, cw.x, fmaf(v3, cw.y, dot1));
            }
        }
        dot0 += __shfl_xor_sync(0xffffffffu, dot0, 1);
        dot0 += __shfl_xor_sync(0xffffffffu, dot0, 2);
        dot1 += __shfl_xor_sync(0xffffffffu, dot1, 1);
        dot1 += __shfl_xor_sync(0xffffffffu, dot1, 2);
        if (tg == 0) {
            const float w0 = fmaxf(dot0 + c1bf, 0.f);
            const float w1 = fmaxf(dot1 + c1bf, 0.f);
            xacc0 += w0 * (sm->xs[r0 * 3 + 0] - xi0) + w1 * (sm->xs[r1 * 3 + 0] - xi0);
            xacc1 += w0 * (sm->xs[r0 * 3 + 1] - xi1) + w1 * (sm->xs[r1 * 3 + 1] - xi1);
            xacc2 += w0 * (sm->xs[r0 * 3 + 2] - xi2) + w1 * (sm->xs[r1 * 3 + 2] - xi2);
        }
    }

    // ---- reduce coordinate update ----
#pragma unroll
    for (int off = 16; off; off >>= 1) {
        xacc0 += __shfl_down_sync(0xffffffffu, xacc0, off);
        xacc1 += __shfl_down_sync(0xffffffffu, xacc1, off);
        xacc2 += __shfl_down_sync(0xffffffffu, xacc2, off);
    }
    if (lane == 0) {
        atomicAdd(&sm->xsum[0], xacc0);
        atomicAdd(&sm->xsum[1], xacc1);
        atomicAdd(&sm->xsum[2], xacc2);
    }
    __syncthreads();   // stage + xsum complete

    // ---- m_node from staged rows ----
    if (t < DMC) {
        float m = 0.f;
#pragma unroll
        for (int s = 0; s < KNN; s++) m += sm->stage[s][t];
        sm->mnode[t] = m;
    }
    __syncthreads();

    // ---- outputs ----
    if (t < 3) out[bi * 3 + t] = sm->xs[i * 3 + t] + sm->xsum[t];
    if (t < DD) {
        float acc = 0.f;
        const float* hrow = h + bi * DD;
#pragma unroll
        for (int k = 0; k < DD; k++) acc = fmaf(hrow[k], n0W[k * DD + t], acc);
#pragma unroll
        for (int k = 0; k < DMC; k++) acc = fmaf(sm->mnode[k], n0W[(DD + k) * DD + t], acc);
        const float v = (acc + n0b[t]) * n0s[t] + n0t[t];
        out[NB * NN * 3 + bi * DD + t] = fmaxf(v, 0.f);
    }
}

// ---------------------------------------------------------------------------
extern "C" void kernel_launch(void* const* d_in, const int* in_sizes, int n_in,
                              void* d_out, int out_size) {
    const float* x   = (const float*)d_in[0];
    const float* h   = (const float*)d_in[1];
    const float* e0W = (const float*)d_in[2];
    const float* e0b = (const float*)d_in[3];
    const float* e0s = (const float*)d_in[4];
    const float* e0t = (const float*)d_in[5];
    const float* e1W = (const float*)d_in[6];
    const float* e1b = (const float*)d_in[7];
    const float* e1s = (const float*)d_in[8];
    const float* e1t = (const float*)d_in[9];
    const float* c0W = (const float*)d_in[10];
    const float* c0b = (const float*)d_in[11];
    const float* c0s = (const float*)d_in[12];
    const float* c0t = (const float*)d_in[13];
    const float* c1W = (const float*)d_in[14];
    const float* c1b = (const float*)d_in[15];
    const float* c1s = (const float*)d_in[16];
    const float* c1t = (const float*)d_in[17];
    const float* n0W = (const float*)d_in[18];
    const float* n0b = (const float*)d_in[19];
    const float* n0s = (const float*)d_in[20];
    const float* n0t = (const float*)d_in[21];
    float* out = (float*)d_out;

    static_assert(sizeof(SmemLayout) < 76 * 1024, "smem too big for 3 CTAs");
    cudaFuncSetAttribute(egnn_main_kernel,
                         cudaFuncAttributeMaxDynamicSharedMemorySize,
                         (int)sizeof(SmemLayout));

    precompute_kernel<<<NB * NN, 64>>>(h, e0W, e0b, e0s, e0t);
    egnn_main_kernel<<<NB * NN, THREADS, sizeof(SmemLayout)>>>(
        x, h, e0W, e0s,
        e1W, e1b, e1s, e1t,
        c0W, c0b, c0s, c0t,
        c1W, c1b, c1s, c1t,
        n0W, n0b, n0s, n0t,
        out);
}

// round 17
// speedup vs baseline: 1.8164x; 1.0869x over previous
#include <cuda_runtime.h>
#include <cuda_fp16.h>
#include <cstdint>

// EGNN layer: B=2, N=768, D=32, DM=64, K=16
#define NB 2
#define NN 768
#define DD 32
#define DMC 64
#define KNN 16
#define TJ 128
#define NTILES (NN / TJ)
#define THREADS 256
#define NRB (NN / 16)            // 48 row-blocks per batch

typedef unsigned int u32;
typedef unsigned long long u64;

__device__ __forceinline__ u32 packpair_h(float v0, float v1) {
    __half2 h = __floats2half2_rn(v0, v1);
    return *reinterpret_cast<u32*>(&h);
}

// m16n8k16 row.col f32.f16.f16.f32
__device__ __forceinline__ void mma16816(float* c, const u32* a, u32 b0, u32 b1) {
    asm volatile(
        "mma.sync.aligned.m16n8k16.row.col.f32.f16.f16.f32 "
        "{%0,%1,%2,%3}, {%4,%5,%6,%7}, {%8,%9}, {%0,%1,%2,%3};"
        : "+f"(c[0]), "+f"(c[1]), "+f"(c[2]), "+f"(c[3])
        : "r"(a[0]), "r"(a[1]), "r"(a[2]), "r"(a[3]), "r"(b0), "r"(b1));
}

// Per-node precomputed e0 partials (folded with BN affine)
// g_As2: fragment-order layout (see precompute scatter below).
__device__ float4 g_As2[NB * NRB * 8 * 32];
__device__ float  g_Bs[NB * NN * DMC];   // (h_i @ W_mid + b0) * s0 + t0

__global__ void precompute_kernel(const float* __restrict__ h,
                                  const float* __restrict__ e0W,
                                  const float* __restrict__ e0b,
                                  const float* __restrict__ e0s,
                                  const float* __restrict__ e0t) {
    __shared__ float hv[DD];
    const int node = blockIdx.x;          // b*NN + n
    const int c = threadIdx.x;            // 0..63
    if (c < DD) hv[c] = h[node * DD + c];
    __syncthreads();
    float a1 = 0.f, a2 = 0.f;
#pragma unroll
    for (int d = 0; d < DD; d++) {
        const float hh = hv[d];
        a1 = fmaf(hh, e0W[d * DMC + c], a1);
        a2 = fmaf(hh, e0W[(DD + d) * DMC + c], a2);
    }
    const float s = e0s[c];
    // scatter As into fragment layout
    const int b = node / NN;
    const int n = node - b * NN;
    const int R = n >> 4;
    const int rl = n & 15;
    const int g = rl & 7;
    const int hiRow = rl >> 3;            // 0 -> (x,y) slot, 1 -> (z,w) slot
    const int ks = c >> 4;
    const int rem = c & 15;
    const int e = rem >> 3;
    const int tg = (rem >> 1) & 3;
    const int p = rem & 1;
    const int lane = 4 * g + tg;
    float* dst = reinterpret_cast<float*>(
        &g_As2[((b * NRB + R) * 8 + ks * 2 + e) * 32 + lane]);
    dst[hiRow * 2 + p] = a1 * s;
    g_Bs[node * DMC + c] = (a2 + e0b[c]) * s + e0t[c];
}

// ---------------------------------------------------------------------------
// B-fragment smem (single fp16, paired-nt layout for LDS.128):
//   B[(ks*4 + (nt>>1))*64 + lane*2 + (nt&1)] = u64{ half2(k0,k0+1|n), half2(k0+8,k0+9|n) }
struct __align__(16) SmemLayout {
    u64 B1[1024];                // e1W folded fp16  (8KB)
    u64 B2[1024];                // c0W folded fp16  (8KB)
    float xs[NN * 3];
    float d2all[NN];
    float stage[KNN][DMC];       // f2 rows of selected neighbors
    float Bsi[DMC], wds[DMC], bias1[DMC], bias2[DMC], c1wf[DMC], mnode[DMC];
    int   slotmap[NN];
    float selval[KNN];
    float xsum[3];
    float redv[8];
    int   redi[8];
    int   seli[KNN];
};

__global__ void __launch_bounds__(THREADS, 3)
egnn_main_kernel(const float* __restrict__ x, const float* __restrict__ h,
                 const float* __restrict__ e0W, const float* __restrict__ e0s,
                 const float* __restrict__ e1W, const float* __restrict__ e1b,
                 const float* __restrict__ e1s, const float* __restrict__ e1t,
                 const float* __restrict__ c0W, const float* __restrict__ c0b,
                 const float* __restrict__ c0s, const float* __restrict__ c0t,
                 const float* __restrict__ c1W, const float* __restrict__ c1b,
                 const float* __restrict__ c1s, const float* __restrict__ c1t,
                 const float* __restrict__ n0W, const float* __restrict__ n0b,
                 const float* __restrict__ n0s, const float* __restrict__ n0t,
                 float* __restrict__ out) {
    extern __shared__ char smraw[];
    SmemLayout* sm = reinterpret_cast<SmemLayout*>(smraw);

    const int bi = blockIdx.x;
    const int b  = bi / NN;
    const int i  = bi - b * NN;
    const int t  = threadIdx.x;
    const int w  = t >> 5;
    const int lane = t & 31;
    const int g  = lane >> 2;
    const int tg = lane & 3;

    // ---- fold weights into paired per-lane fp16 B-fragment layout ----
    for (int e = t; e < 1024; e += THREADS) {
        const int l  = e & 31;
        const int nt = (e >> 5) & 7;
        const int ks = e >> 8;
        const int k0 = ks * 16 + 2 * (l & 3);
        const int n  = nt * 8 + (l >> 2);
        const int dst = (ks * 4 + (nt >> 1)) * 64 + l * 2 + (nt & 1);
        const float s1 = e1s[n], s2 = c0s[n];
        u32 a0 = packpair_h(e1W[k0 * DMC + n] * s1, e1W[(k0 + 1) * DMC + n] * s1);
        u32 a1 = packpair_h(e1W[(k0 + 8) * DMC + n] * s1, e1W[(k0 + 9) * DMC + n] * s1);
        sm->B1[dst] = (u64)a0 | ((u64)a1 << 32);
        a0 = packpair_h(c0W[k0 * DMC + n] * s2, c0W[(k0 + 1) * DMC + n] * s2);
        a1 = packpair_h(c0W[(k0 + 8) * DMC + n] * s2, c0W[(k0 + 9) * DMC + n] * s2);
        sm->B2[dst] = (u64)a0 | ((u64)a1 << 32);
    }
    if (t < DMC) {
        sm->bias1[t] = e1b[t] * e1s[t] + e1t[t];
        sm->bias2[t] = c0b[t] * c0s[t] + c0t[t];
        sm->Bsi[t]   = g_Bs[bi * DMC + t];
        sm->wds[t]   = e0W[2 * DD * DMC + t] * e0s[t];
        sm->c1wf[t]  = c1W[t] * c1s[0];
    }
    for (int e = t; e < NN * 3; e += THREADS) sm->xs[e] = x[b * NN * 3 + e];
    for (int e = t; e < NN; e += THREADS) sm->slotmap[e] = -1;
    if (t == 0) { sm->xsum[0] = 0.f; sm->xsum[1] = 0.f; sm->xsum[2] = 0.f; }
    const float c1bf = c1b[0] * c1s[0] + c1t[0];
    __syncthreads();

    const float xi0 = sm->xs[i * 3 + 0];
    const float xi1 = sm->xs[i * 3 + 1];
    const float xi2 = sm->xs[i * 3 + 2];

    // ---- distances ----
    for (int j = t; j < NN; j += THREADS) {
        const float dx = sm->xs[j * 3 + 0] - xi0;
        const float dy = sm->xs[j * 3 + 1] - xi1;
        const float dz = sm->xs[j * 3 + 2] - xi2;
        sm->d2all[j] = dx * dx + dy * dy + dz * dz;
    }
    __syncthreads();

    // ---- kNN: 16 sequential block argmins (tie-break lower index) ----
    const float INF = __int_as_float(0x7f800000);
    for (int s = 0; s < KNN; s++) {
        float bv = INF; int bidx = NN;
#pragma unroll
        for (int j = t; j < NN; j += THREADS) {
            const float v = sm->d2all[j];
            if (v < bv || (v == bv && j < bidx)) { bv = v; bidx = j; }
        }
#pragma unroll
        for (int off = 16; off; off >>= 1) {
            const float ov = __shfl_down_sync(0xffffffffu, bv, off);
            const int   oi = __shfl_down_sync(0xffffffffu, bidx, off);
            if (ov < bv || (ov == bv && oi < bidx)) { bv = ov; bidx = oi; }
        }
        if (lane == 0) { sm->redv[w] = bv; sm->redi[w] = bidx; }
        __syncthreads();
        if (t == 0) {
            float fv = sm->redv[0]; int fi = sm->redi[0];
#pragma unroll
            for (int q = 1; q < 8; q++) {
                const float wv = sm->redv[q]; const int wi = sm->redi[q];
                if (wv < fv || (wv == fv && wi < fi)) { fv = wv; fi = wi; }
            }
            sm->seli[s] = fi;
            sm->selval[s] = fv;
            sm->d2all[fi] = INF;
        }
        __syncthreads();
    }
    if (t < KNN) {
        sm->d2all[sm->seli[t]] = sm->selval[t];   // restore
        sm->slotmap[sm->seli[t]] = t;
    }
    __syncthreads();

    // ---- barrier-free mainloop: 8 warps x 16 rows, TJ=128 ----
    float xacc0 = 0.f, xacc1 = 0.f, xacc2 = 0.f;

    for (int tile = 0; tile < NTILES; tile++) {
        const int j0 = tile * TJ;
        const int r0 = j0 + w * 16 + g;
        const int r1 = r0 + 8;
        const float d2a = sm->d2all[r0];
        const float d2b = sm->d2all[r1];
        // fragment-layout A base for this warp's 16-row block
        const float4* Afrag = &g_As2[((b * NRB + tile * 8 + w) * 8) * 32 + lane];

        // build A1-fragments in registers: f1 = relu(As + Bsi + d2*wds), single fp16
        u32 ah[16];
#pragma unroll
        for (int ks = 0; ks < 4; ks++) {
            const int k0 = ks * 16 + 2 * tg;
            const float2 bs0 = *reinterpret_cast<const float2*>(&sm->Bsi[k0]);
            const float2 bs1 = *reinterpret_cast<const float2*>(&sm->Bsi[k0 + 8]);
            const float2 wd0 = *reinterpret_cast<const float2*>(&sm->wds[k0]);
            const float2 wd1 = *reinterpret_cast<const float2*>(&sm->wds[k0 + 8]);
            const float4 fa = Afrag[(ks * 2 + 0) * 32];   // rows r0,r1 @ k0,k0+1
            const float4 fb = Afrag[(ks * 2 + 1) * 32];   // rows r0,r1 @ k0+8,k0+9
            float v0 = fmaxf(fmaf(d2a, wd0.x, fa.x + bs0.x), 0.f);
            float v1 = fmaxf(fmaf(d2a, wd0.y, fa.y + bs0.y), 0.f);
            ah[ks * 4 + 0] = packpair_h(v0, v1);
            v0 = fmaxf(fmaf(d2b, wd0.x, fa.z + bs0.x), 0.f);
            v1 = fmaxf(fmaf(d2b, wd0.y, fa.w + bs0.y), 0.f);
            ah[ks * 4 + 1] = packpair_h(v0, v1);
            v0 = fmaxf(fmaf(d2a, wd1.x, fb.x + bs1.x), 0.f);
            v1 = fmaxf(fmaf(d2a, wd1.y, fb.y + bs1.y), 0.f);
            ah[ks * 4 + 2] = packpair_h(v0, v1);
            v0 = fmaxf(fmaf(d2b, wd1.x, fb.z + bs1.x), 0.f);
            v1 = fmaxf(fmaf(d2b, wd1.y, fb.w + bs1.y), 0.f);
            ah[ks * 4 + 3] = packpair_h(v0, v1);
        }

        const int slot0 = sm->slotmap[r0];
        const int slot1 = sm->slotmap[r1];
        u32 ah2[16];                        // A2: single fp16

        // GEMM 1 in two N-halves; B via paired LDS.128, 1 MMA per nt-sub
#pragma unroll
        for (int hf = 0; hf < 2; hf++) {
            float acc[16];
#pragma unroll
            for (int q = 0; q < 16; q++) acc[q] = 0.f;
#pragma unroll
            for (int ks = 0; ks < 4; ks++) {
#pragma unroll
                for (int npl = 0; npl < 2; npl++) {
                    const int np = hf * 2 + npl;
                    const ulonglong2 b2 = *reinterpret_cast<const ulonglong2*>(
                        &sm->B1[(ks * 4 + np) * 64 + 2 * lane]);
#pragma unroll
                    for (int sub = 0; sub < 2; sub++) {
                        const u64 bb = sub ? b2.y : b2.x;
                        const u32 b0 = (u32)bb, b1 = (u32)(bb >> 32);
                        const int ntl = 2 * npl + sub;
                        mma16816(acc + ntl * 4, ah + ks * 4, b0, b1);
                    }
                }
            }
            // epilogue half: relu+bias, stage, pack single-fp16 A2 frags
#pragma unroll
            for (int ntl = 0; ntl < 4; ntl++) {
                const int nt = hf * 4 + ntl;
                const int n0 = nt * 8 + 2 * tg;
                const float2 bb = *reinterpret_cast<const float2*>(&sm->bias1[n0]);
                const float v0 = fmaxf(acc[ntl * 4 + 0] + bb.x, 0.f);
                const float v1 = fmaxf(acc[ntl * 4 + 1] + bb.y, 0.f);
                const float v2 = fmaxf(acc[ntl * 4 + 2] + bb.x, 0.f);
                const float v3 = fmaxf(acc[ntl * 4 + 3] + bb.y, 0.f);
                if (slot0 >= 0)
                    *reinterpret_cast<float2*>(&sm->stage[slot0][n0]) = make_float2(v0, v1);
                if (slot1 >= 0)
                    *reinterpret_cast<float2*>(&sm->stage[slot1][n0]) = make_float2(v2, v3);
                const int ks2 = nt >> 1, hh = (nt & 1) * 2;
                ah2[ks2 * 4 + hh + 0] = packpair_h(v0, v1);
                ah2[ks2 * 4 + hh + 1] = packpair_h(v2, v3);
            }
        }

        // GEMM 2 in two N-halves + c1 dot (single-term A)
        float dot0 = 0.f, dot1 = 0.f;
#pragma unroll
        for (int hf = 0; hf < 2; hf++) {
            float acc[16];
#pragma unroll
            for (int q = 0; q < 16; q++) acc[q] = 0.f;
#pragma unroll
            for (int ks = 0; ks < 4; ks++) {
#pragma unroll
                for (int npl = 0; npl < 2; npl++) {
                    const int np = hf * 2 + npl;
                    const ulonglong2 b2 = *reinterpret_cast<const ulonglong2*>(
                        &sm->B2[(ks * 4 + np) * 64 + 2 * lane]);
#pragma unroll
                    for (int sub = 0; sub < 2; sub++) {
                        const u64 bb = sub ? b2.y : b2.x;
                        const u32 b0 = (u32)bb, b1 = (u32)(bb >> 32);
                        const int ntl = 2 * npl + sub;
                        mma16816(acc + ntl * 4, ah2 + ks * 4, b0, b1);
                    }
                }
            }
#pragma unroll
            for (int ntl = 0; ntl < 4; ntl++) {
                const int nt = hf * 4 + ntl;
                const int n0 = nt * 8 + 2 * tg;
                const float2 bb = *reinterpret_cast<const float2*>(&sm->bias2[n0]);
                const float2 cw = *reinterpret_cast<const float2*>(&sm->c1wf[n0]);
                const float v0 = fmaxf(acc[ntl * 4 + 0] + bb.x, 0.f);
                const float v1 = fmaxf(acc[ntl * 4 + 1] + bb.y, 0.f);
                const float v2 = fmaxf(acc[ntl * 4 + 2] + bb.x, 0.f);
                const float v3 = fmaxf(acc[ntl * 4 + 3] + bb.y, 0.f);
                dot0 = fmaf(v0, cw.x, fmaf(v1, cw.y, dot0));
                dot1 = fmaf(v2, cw.x, fmaf(v3, cw.y, dot1));
            }
        }
        dot0 += __shfl_xor_sync(0xffffffffu, dot0, 1);
        dot0 += __shfl_xor_sync(0xffffffffu, dot0, 2);
        dot1 += __shfl_xor_sync(0xffffffffu, dot1, 1);
        dot1 += __shfl_xor_sync(0xffffffffu, dot1, 2);
        if (tg == 0) {
            const float w0 = fmaxf(dot0 + c1bf, 0.f);
            const float w1 = fmaxf(dot1 + c1bf, 0.f);
            xacc0 += w0 * (sm->xs[r0 * 3 + 0] - xi0) + w1 * (sm->xs[r1 * 3 + 0] - xi0);
            xacc1 += w0 * (sm->xs[r0 * 3 + 1] - xi1) + w1 * (sm->xs[r1 * 3 + 1] - xi1);
            xacc2 += w0 * (sm->xs[r0 * 3 + 2] - xi2) + w1 * (sm->xs[r1 * 3 + 2] - xi2);
        }
    }

    // ---- reduce coordinate update ----
#pragma unroll
    for (int off = 16; off; off >>= 1) {
        xacc0 += __shfl_down_sync(0xffffffffu, xacc0, off);
        xacc1 += __shfl_down_sync(0xffffffffu, xacc1, off);
        xacc2 += __shfl_down_sync(0xffffffffu, xacc2, off);
    }
    if (lane == 0) {
        atomicAdd(&sm->xsum[0], xacc0);
        atomicAdd(&sm->xsum[1], xacc1);
        atomicAdd(&sm->xsum[2], xacc2);
    }
    __syncthreads();   // stage + xsum complete

    // ---- m_node from staged rows ----
    if (t < DMC) {
        float m = 0.f;
#pragma unroll
        for (int s = 0; s < KNN; s++) m += sm->stage[s][t];
        sm->mnode[t] = m;
    }
    __syncthreads();

    // ---- outputs ----
    if (t < 3) out[bi * 3 + t] = sm->xs[i * 3 + t] + sm->xsum[t];
    if (t < DD) {
        float acc = 0.f;
        const float* hrow = h + bi * DD;
#pragma unroll
        for (int k = 0; k < DD; k++) acc = fmaf(hrow[k], n0W[k * DD + t], acc);
#pragma unroll
        for (int k = 0; k < DMC; k++) acc = fmaf(sm->mnode[k], n0W[(DD + k) * DD + t], acc);
        const float v = (acc + n0b[t]) * n0s[t] + n0t[t];
        out[NB * NN * 3 + bi * DD + t] = fmaxf(v, 0.f);
    }
}

// ---------------------------------------------------------------------------
extern "C" void kernel_launch(void* const* d_in, const int* in_sizes, int n_in,
                              void* d_out, int out_size) {
    const float* x   = (const float*)d_in[0];
    const float* h   = (const float*)d_in[1];
    const float* e0W = (const float*)d_in[2];
    const float* e0b = (const float*)d_in[3];
    const float* e0s = (const float*)d_in[4];
    const float* e0t = (const float*)d_in[5];
    const float* e1W = (const float*)d_in[6];
    const float* e1b = (const float*)d_in[7];
    const float* e1s = (const float*)d_in[8];
    const float* e1t = (const float*)d_in[9];
    const float* c0W = (const float*)d_in[10];
    const float* c0b = (const float*)d_in[11];
    const float* c0s = (const float*)d_in[12];
    const float* c0t = (const float*)d_in[13];
    const float* c1W = (const float*)d_in[14];
    const float* c1b = (const float*)d_in[15];
    const float* c1s = (const float*)d_in[16];
    const float* c1t = (const float*)d_in[17];
    const float* n0W = (const float*)d_in[18];
    const float* n0b = (const float*)d_in[19];
    const float* n0s = (const float*)d_in[20];
    const float* n0t = (const float*)d_in[21];
    float* out = (float*)d_out;

    static_assert(sizeof(SmemLayout) < 76 * 1024, "smem too big for 3 CTAs");
    cudaFuncSetAttribute(egnn_main_kernel,
                         cudaFuncAttributeMaxDynamicSharedMemorySize,
                         (int)sizeof(SmemLayout));

    precompute_kernel<<<NB * NN, 64>>>(h, e0W, e0b, e0s, e0t);
    egnn_main_kernel<<<NB * NN, THREADS, sizeof(SmemLayout)>>>(
        x, h, e0W, e0s,
        e1W, e1b, e1s, e1t,
        c0W, c0b, c0s, c0t,
        c1W, c1b, c1s, c1t,
        n0W, n0b, n0s, n0t,
        out);
}